// round 3
// baseline (speedup 1.0000x reference)
#include <cuda_runtime.h>
#include <math.h>

// Problem constants
#define EDIM   768
#define SDIM   256
#define BATCH  128
#define NROWS  (BATCH * SDIM)   // 32768
#define HDIM   (EDIM / 2)       // 384
#define NCLS   4

// Scratch (static device globals — no allocation APIs allowed)
__device__ float g_qW[BATCH * EDIM];                    // q @ W1_top + b1
__device__ float g_H1[(size_t)NROWS * EDIM];            // 96 MB
__device__ float g_H2[(size_t)NROWS * HDIM];            // 48 MB
__device__ float g_preds[NROWS * NCLS];

__device__ __forceinline__ float gelu_exact(float x) {
    return 0.5f * x * (1.0f + erff(x * 0.70710678118654752f));
}

// ---------------------------------------------------------------------------
// Tiled SIMT fp32 GEMM: C[M,N] = epilogue(A[M,K] @ B[K,N])
// BM=BN=128, BK=32, 256 threads, each computes 8x8.
// EPI 0: += extra[col]                      (bias; used for qW precompute)
// EPI 1: gelu(x + extra[(row>>8)*EDIM+col]) (add per-batch qW row; row>>8 = b)
// EPI 2: gelu(x + extra[col])               (bias + gelu)
// All dims divide tile sizes exactly for this problem — no bounds checks.
// ---------------------------------------------------------------------------
template <int EPI>
__global__ void __launch_bounds__(256) gemm_k(
    const float* __restrict__ A, const float* __restrict__ B,
    float* __restrict__ C, const float* __restrict__ extra,
    int M, int N, int K)
{
    constexpr int BM = 128, BN = 128, BK = 32;
    __shared__ float As[BK][BM + 4];
    __shared__ float Bs[BK][BN];

    const int bm  = blockIdx.y * BM;
    const int bn  = blockIdx.x * BN;
    const int tid = threadIdx.x;
    const int tr  = tid >> 4;     // 0..15
    const int tc  = tid & 15;     // 0..15
    const int row0 = tr * 8;
    const int col0 = tc * 8;

    float acc[8][8];
    #pragma unroll
    for (int i = 0; i < 8; i++)
        #pragma unroll
        for (int j = 0; j < 8; j++) acc[i][j] = 0.0f;

    const float* Aptr = A + (size_t)bm * K;
    const float* Bptr = B + bn;

    for (int k0 = 0; k0 < K; k0 += BK) {
        // Load A tile 128x32 (4096 elems, 16/thread), transposed into As[k][m]
        #pragma unroll
        for (int i = 0; i < 16; i++) {
            int idx = tid + i * 256;
            int ar = idx >> 5;       // row in tile (0..127)
            int ak = idx & 31;       // k in tile (0..31)
            As[ak][ar] = Aptr[(size_t)ar * K + k0 + ak];
        }
        // Load B tile 32x128 (4096 elems, 16/thread)
        #pragma unroll
        for (int i = 0; i < 16; i++) {
            int idx = tid + i * 256;
            int bk  = idx >> 7;      // k in tile (0..31)
            int bnn = idx & 127;     // col in tile
            Bs[bk][bnn] = Bptr[(size_t)(k0 + bk) * N + bnn];
        }
        __syncthreads();

        #pragma unroll
        for (int kk = 0; kk < BK; kk++) {
            float4 a0 = *(const float4*)&As[kk][row0];
            float4 a1 = *(const float4*)&As[kk][row0 + 4];
            float4 b0 = *(const float4*)&Bs[kk][col0];
            float4 b1 = *(const float4*)&Bs[kk][col0 + 4];
            float av[8] = {a0.x, a0.y, a0.z, a0.w, a1.x, a1.y, a1.z, a1.w};
            float bv[8] = {b0.x, b0.y, b0.z, b0.w, b1.x, b1.y, b1.z, b1.w};
            #pragma unroll
            for (int i = 0; i < 8; i++)
                #pragma unroll
                for (int j = 0; j < 8; j++)
                    acc[i][j] = fmaf(av[i], bv[j], acc[i][j]);
        }
        __syncthreads();
    }

    // Epilogue + vectorized store
    #pragma unroll
    for (int i = 0; i < 8; i++) {
        int row = bm + row0 + i;
        float v[8];
        #pragma unroll
        for (int j = 0; j < 8; j++) {
            int col = bn + col0 + j;
            float x = acc[i][j];
            if (EPI == 0) {
                x += extra[col];
            } else if (EPI == 1) {
                x += extra[(row >> 8) * EDIM + col];   // qW[b][col]
                x = gelu_exact(x);
            } else {
                x += extra[col];
                x = gelu_exact(x);
            }
            v[j] = x;
        }
        float* cp = C + (size_t)row * N + bn + col0;
        *(float4*)cp       = make_float4(v[0], v[1], v[2], v[3]);
        *(float4*)(cp + 4) = make_float4(v[4], v[5], v[6], v[7]);
    }
}

// ---------------------------------------------------------------------------
// Final projection [384 -> 4] + softmax. One warp per row.
// ---------------------------------------------------------------------------
__global__ void __launch_bounds__(256) logits_softmax_k(
    const float* __restrict__ H2, const float* __restrict__ W3,
    const float* __restrict__ b3, float* __restrict__ preds)
{
    int warp = (blockIdx.x * blockDim.x + threadIdx.x) >> 5;
    int lane = threadIdx.x & 31;
    if (warp >= NROWS) return;

    const float* h = H2 + (size_t)warp * HDIM;
    float a0 = 0.f, a1 = 0.f, a2 = 0.f, a3 = 0.f;
    #pragma unroll
    for (int j = 0; j < HDIM / 32; j++) {
        int m = lane + j * 32;
        float hv = h[m];
        float4 w = *(const float4*)(W3 + m * 4);
        a0 = fmaf(hv, w.x, a0);
        a1 = fmaf(hv, w.y, a1);
        a2 = fmaf(hv, w.z, a2);
        a3 = fmaf(hv, w.w, a3);
    }
    #pragma unroll
    for (int off = 16; off; off >>= 1) {
        a0 += __shfl_xor_sync(0xffffffffu, a0, off);
        a1 += __shfl_xor_sync(0xffffffffu, a1, off);
        a2 += __shfl_xor_sync(0xffffffffu, a2, off);
        a3 += __shfl_xor_sync(0xffffffffu, a3, off);
    }
    if (lane == 0) {
        float l0 = a0 + b3[0], l1 = a1 + b3[1], l2 = a2 + b3[2], l3 = a3 + b3[3];
        float mx = fmaxf(fmaxf(l0, l1), fmaxf(l2, l3));
        float e0 = expf(l0 - mx), e1 = expf(l1 - mx), e2 = expf(l2 - mx), e3 = expf(l3 - mx);
        float inv = 1.0f / (e0 + e1 + e2 + e3);
        *(float4*)(preds + (size_t)warp * 4) =
            make_float4(e0 * inv, e1 * inv, e2 * inv, e3 * inv);
    }
}

// ---------------------------------------------------------------------------
// Per-bag aggregation. One block per b, threads 0..3 handle one class each.
//   s[i][c]  = exclusive class-cumsum of preds[b,i,:]
//   L[i]     = prefix(i) * suffix(i)   (leave-one-out product over segments)
//   cpL      = running product of L over i
//   out      = sum_i p*cpL / 4 + prod_i p
// ---------------------------------------------------------------------------
__global__ void aggregate_k(const float* __restrict__ preds,
                            const int* __restrict__ nseg,
                            float* __restrict__ out)
{
    int b = blockIdx.x;
    int c = threadIdx.x;
    __shared__ float ss[NCLS][SDIM];
    __shared__ float suf[NCLS][SDIM];
    if (c >= NCLS) return;

    int n = nseg[b];
    const float4* p = (const float4*)(preds + (size_t)b * SDIM * NCLS);

    // exclusive cumsum over classes (masked positions excluded by loop bound)
    for (int i = 0; i < n; i++) {
        float4 pv = p[i];
        float sv = (c == 0) ? 0.0f
                 : (c == 1) ? pv.x
                 : (c == 2) ? pv.x + pv.y
                            : pv.x + pv.y + pv.z;
        ss[c][i] = sv;
    }
    // suffix products
    float r = 1.0f;
    for (int i = n - 1; i >= 0; i--) {
        suf[c][i] = r;
        r *= ss[c][i];
    }
    // forward pass: prefix running product, cpL, sums
    float pre = 1.0f, cpl = 1.0f, sum = 0.0f, prodp = 1.0f;
    for (int i = 0; i < n; i++) {
        float4 pv = p[i];
        float pc = (c == 0) ? pv.x : (c == 1) ? pv.y : (c == 2) ? pv.z : pv.w;
        float L = pre * suf[c][i];
        cpl *= L;
        sum = fmaf(pc, cpl, sum);
        prodp *= pc;
        pre *= ss[c][i];
    }
    out[b * NCLS + c] = sum * 0.25f + prodp;
}

// ---------------------------------------------------------------------------
extern "C" void kernel_launch(void* const* d_in, const int* in_sizes, int n_in,
                              void* d_out, int out_size)
{
    const float* questions = (const float*)d_in[0];
    const float* segments  = (const float*)d_in[1];
    const float* W1        = (const float*)d_in[2];
    const float* b1        = (const float*)d_in[3];
    const float* W2        = (const float*)d_in[4];
    const float* b2        = (const float*)d_in[5];
    const float* W3        = (const float*)d_in[6];
    const float* b3        = (const float*)d_in[7];
    const int*   nseg      = (const int*)d_in[8];
    float* out = (float*)d_out;

    float *pqW, *pH1, *pH2, *ppreds;
    cudaGetSymbolAddress((void**)&pqW,    g_qW);
    cudaGetSymbolAddress((void**)&pH1,    g_H1);
    cudaGetSymbolAddress((void**)&pH2,    g_H2);
    cudaGetSymbolAddress((void**)&ppreds, g_preds);

    // 1) qW[b] = q[b] @ W1[0:768] + b1        (tiny: 128x768x768)
    gemm_k<0><<<dim3(EDIM / 128, BATCH / 128), 256>>>(
        questions, W1, pqW, b1, BATCH, EDIM, EDIM);

    // 2) H1 = gelu(seg @ W1[768:1536] + qW[b])  (32768x768x768)
    gemm_k<1><<<dim3(EDIM / 128, NROWS / 128), 256>>>(
        segments, W1 + (size_t)EDIM * EDIM, pH1, pqW, NROWS, EDIM, EDIM);

    // 3) H2 = gelu(H1 @ W2 + b2)                (32768x384x768)
    gemm_k<2><<<dim3(HDIM / 128, NROWS / 128), 256>>>(
        pH1, W2, pH2, b2, NROWS, HDIM, EDIM);

    // 4) preds = softmax(H2 @ W3 + b3)
    logits_softmax_k<<<(NROWS * 32) / 256, 256>>>(pH2, W3, b3, ppreds);

    // 5) per-bag aggregation
    aggregate_k<<<BATCH, 32>>>(ppreds, nseg, out);
}

// round 4
// speedup vs baseline: 1.9200x; 1.9200x over previous
#include <cuda_runtime.h>
#include <math.h>

// Problem constants
#define EDIM   768
#define SDIM   256
#define BATCH  128
#define NROWS  (BATCH * SDIM)   // 32768
#define HDIM   (EDIM / 2)       // 384
#define NCLS   4

// Scratch (static device globals — no allocation APIs allowed)
__device__ float g_qW[BATCH * EDIM];                    // q @ W1_top + b1
__device__ float g_H1[(size_t)NROWS * EDIM];            // 96 MB
__device__ float g_H2[(size_t)NROWS * HDIM];            // 48 MB
__device__ float g_preds[NROWS * NCLS];

__device__ __forceinline__ float gelu_exact(float x) {
    return 0.5f * x * (1.0f + erff(x * 0.70710678118654752f));
}

__device__ __forceinline__ unsigned f2tf32(float x) {
    unsigned r;
    asm("cvt.rna.tf32.f32 %0, %1;" : "=r"(r) : "f"(x));
    return r;
}

__device__ __forceinline__ void mma_tf32(float* d, const unsigned* a, const unsigned* b) {
    asm volatile(
        "mma.sync.aligned.m16n8k8.row.col.f32.tf32.tf32.f32 "
        "{%0,%1,%2,%3}, {%4,%5,%6,%7}, {%8,%9}, {%0,%1,%2,%3};\n"
        : "+f"(d[0]), "+f"(d[1]), "+f"(d[2]), "+f"(d[3])
        : "r"(a[0]), "r"(a[1]), "r"(a[2]), "r"(a[3]), "r"(b[0]), "r"(b[1]));
}

// ---------------------------------------------------------------------------
// tf32 tensor-core GEMM: C[M,N] = epilogue(A[M,K] @ B[K,N])
// BM=BN=128, BK=32, 256 threads (8 warps), warp tile 64x32 via m16n8k8.
// Warp grid 2(m) x 4(n). A in smem [m][k] pad 36; B in smem [k][n] pad 136.
// Fragment smem loads are conflict-free:
//   A: addr%32 = 4*gid + tig (all lanes distinct)
//   B: addr%32 = 8*tig + gid (all lanes distinct)
// EPI 0: += extra[col]                      (bias; for qW precompute)
// EPI 1: gelu(x + extra[(row>>8)*EDIM+col]) (per-batch qW row)
// EPI 2: gelu(x + extra[col])               (bias + gelu)
// All dims divide tile sizes exactly; no bounds checks.
// ---------------------------------------------------------------------------
template <int EPI>
__global__ void __launch_bounds__(256) gemm_tc(
    const float* __restrict__ A, const float* __restrict__ B,
    float* __restrict__ C, const float* __restrict__ extra,
    int M, int N, int K)
{
    constexpr int BM = 128, BN = 128, BK = 32;
    constexpr int APAD = 36, BPAD = 136;
    __shared__ unsigned As[BM * APAD];   // [m][k], tf32 bits
    __shared__ unsigned Bs[BK * BPAD];   // [k][n], tf32 bits

    const int bm   = blockIdx.y * BM;
    const int bn   = blockIdx.x * BN;
    const int tid  = threadIdx.x;
    const int warp = tid >> 5;
    const int lane = tid & 31;
    const int gid  = lane >> 2;   // 0..7
    const int tig  = lane & 3;    // 0..3
    const int mwarp = (warp >> 2) * 64;   // 0 or 64
    const int nwarp = (warp & 3) * 32;    // 0,32,64,96

    float acc[4][4][4];
    #pragma unroll
    for (int mt = 0; mt < 4; mt++)
        #pragma unroll
        for (int nt = 0; nt < 4; nt++)
            #pragma unroll
            for (int r = 0; r < 4; r++) acc[mt][nt][r] = 0.0f;

    const float* Aptr = A + (size_t)bm * K;
    const float* Bptr = B + bn;

    for (int k0 = 0; k0 < K; k0 += BK) {
        // --- Load A tile 128x32 -> As[m][k] (tf32). 1024 float4, 4/thread.
        #pragma unroll
        for (int i = 0; i < 4; i++) {
            int idx = tid + i * 256;
            int ar = idx >> 3;           // 0..127
            int kq = (idx & 7) * 4;      // 0,4,..,28
            float4 v = *(const float4*)(Aptr + (size_t)ar * K + k0 + kq);
            unsigned* dst = &As[ar * APAD + kq];
            dst[0] = f2tf32(v.x); dst[1] = f2tf32(v.y);
            dst[2] = f2tf32(v.z); dst[3] = f2tf32(v.w);
        }
        // --- Load B tile 32x128 -> Bs[k][n] (tf32). 1024 float4, 4/thread.
        #pragma unroll
        for (int i = 0; i < 4; i++) {
            int idx = tid + i * 256;
            int bk = idx >> 5;           // 0..31
            int nq = (idx & 31) * 4;     // 0,4,..,124
            float4 v = *(const float4*)(Bptr + (size_t)(k0 + bk) * N + nq);
            unsigned* dst = &Bs[bk * BPAD + nq];
            dst[0] = f2tf32(v.x); dst[1] = f2tf32(v.y);
            dst[2] = f2tf32(v.z); dst[3] = f2tf32(v.w);
        }
        __syncthreads();

        #pragma unroll
        for (int ks = 0; ks < BK / 8; ks++) {
            const int k = ks * 8;
            // A fragments: 4 m-tiles x 4 regs
            unsigned af[4][4];
            #pragma unroll
            for (int mt = 0; mt < 4; mt++) {
                int m = mwarp + mt * 16;
                af[mt][0] = As[(m + gid)     * APAD + k + tig];
                af[mt][1] = As[(m + gid + 8) * APAD + k + tig];
                af[mt][2] = As[(m + gid)     * APAD + k + tig + 4];
                af[mt][3] = As[(m + gid + 8) * APAD + k + tig + 4];
            }
            // B fragments: 4 n-tiles x 2 regs
            unsigned bf[4][2];
            #pragma unroll
            for (int nt = 0; nt < 4; nt++) {
                int n = nwarp + nt * 8;
                bf[nt][0] = Bs[(k + tig)     * BPAD + n + gid];
                bf[nt][1] = Bs[(k + tig + 4) * BPAD + n + gid];
            }
            #pragma unroll
            for (int mt = 0; mt < 4; mt++)
                #pragma unroll
                for (int nt = 0; nt < 4; nt++)
                    mma_tf32(acc[mt][nt], af[mt], bf[nt]);
        }
        __syncthreads();
    }

    // --- Epilogue. C fragment: c0,c1 @ (gid, 2tig..2tig+1); c2,c3 @ (gid+8, ..)
    #pragma unroll
    for (int mt = 0; mt < 4; mt++) {
        #pragma unroll
        for (int nt = 0; nt < 4; nt++) {
            int r0 = bm + mwarp + mt * 16 + gid;
            int r1 = r0 + 8;
            int c  = bn + nwarp + nt * 8 + 2 * tig;
            float v0 = acc[mt][nt][0], v1 = acc[mt][nt][1];
            float v2 = acc[mt][nt][2], v3 = acc[mt][nt][3];
            if (EPI == 0) {
                float e0 = extra[c], e1 = extra[c + 1];
                v0 += e0; v1 += e1; v2 += e0; v3 += e1;
            } else if (EPI == 1) {
                const float* ex0 = extra + (r0 >> 8) * EDIM;
                const float* ex1 = extra + (r1 >> 8) * EDIM;
                v0 = gelu_exact(v0 + ex0[c]); v1 = gelu_exact(v1 + ex0[c + 1]);
                v2 = gelu_exact(v2 + ex1[c]); v3 = gelu_exact(v3 + ex1[c + 1]);
            } else {
                float e0 = extra[c], e1 = extra[c + 1];
                v0 = gelu_exact(v0 + e0); v1 = gelu_exact(v1 + e1);
                v2 = gelu_exact(v2 + e0); v3 = gelu_exact(v3 + e1);
            }
            *(float2*)(C + (size_t)r0 * N + c) = make_float2(v0, v1);
            *(float2*)(C + (size_t)r1 * N + c) = make_float2(v2, v3);
        }
    }
}

// ---------------------------------------------------------------------------
// Final projection [384 -> 4] + softmax. One warp per row.
// ---------------------------------------------------------------------------
__global__ void __launch_bounds__(256) logits_softmax_k(
    const float* __restrict__ H2, const float* __restrict__ W3,
    const float* __restrict__ b3, float* __restrict__ preds)
{
    int warp = (blockIdx.x * blockDim.x + threadIdx.x) >> 5;
    int lane = threadIdx.x & 31;
    if (warp >= NROWS) return;

    const float* h = H2 + (size_t)warp * HDIM;
    float a0 = 0.f, a1 = 0.f, a2 = 0.f, a3 = 0.f;
    #pragma unroll
    for (int j = 0; j < HDIM / 32; j++) {
        int m = lane + j * 32;
        float hv = h[m];
        float4 w = *(const float4*)(W3 + m * 4);
        a0 = fmaf(hv, w.x, a0);
        a1 = fmaf(hv, w.y, a1);
        a2 = fmaf(hv, w.z, a2);
        a3 = fmaf(hv, w.w, a3);
    }
    #pragma unroll
    for (int off = 16; off; off >>= 1) {
        a0 += __shfl_xor_sync(0xffffffffu, a0, off);
        a1 += __shfl_xor_sync(0xffffffffu, a1, off);
        a2 += __shfl_xor_sync(0xffffffffu, a2, off);
        a3 += __shfl_xor_sync(0xffffffffu, a3, off);
    }
    if (lane == 0) {
        float l0 = a0 + b3[0], l1 = a1 + b3[1], l2 = a2 + b3[2], l3 = a3 + b3[3];
        float mx = fmaxf(fmaxf(l0, l1), fmaxf(l2, l3));
        float e0 = expf(l0 - mx), e1 = expf(l1 - mx), e2 = expf(l2 - mx), e3 = expf(l3 - mx);
        float inv = 1.0f / (e0 + e1 + e2 + e3);
        *(float4*)(preds + (size_t)warp * 4) =
            make_float4(e0 * inv, e1 * inv, e2 * inv, e3 * inv);
    }
}

// ---------------------------------------------------------------------------
// Per-bag aggregation. One block per b, threads 0..3 handle one class each.
// ---------------------------------------------------------------------------
__global__ void aggregate_k(const float* __restrict__ preds,
                            const int* __restrict__ nseg,
                            float* __restrict__ out)
{
    int b = blockIdx.x;
    int c = threadIdx.x;
    __shared__ float ss[NCLS][SDIM];
    __shared__ float suf[NCLS][SDIM];
    if (c >= NCLS) return;

    int n = nseg[b];
    const float4* p = (const float4*)(preds + (size_t)b * SDIM * NCLS);

    // exclusive cumsum over classes
    for (int i = 0; i < n; i++) {
        float4 pv = p[i];
        float sv = (c == 0) ? 0.0f
                 : (c == 1) ? pv.x
                 : (c == 2) ? pv.x + pv.y
                            : pv.x + pv.y + pv.z;
        ss[c][i] = sv;
    }
    // suffix products
    float r = 1.0f;
    for (int i = n - 1; i >= 0; i--) {
        suf[c][i] = r;
        r *= ss[c][i];
    }
    // forward pass: prefix running product, cpL, sums
    float pre = 1.0f, cpl = 1.0f, sum = 0.0f, prodp = 1.0f;
    for (int i = 0; i < n; i++) {
        float4 pv = p[i];
        float pc = (c == 0) ? pv.x : (c == 1) ? pv.y : (c == 2) ? pv.z : pv.w;
        float L = pre * suf[c][i];
        cpl *= L;
        sum = fmaf(pc, cpl, sum);
        prodp *= pc;
        pre *= ss[c][i];
    }
    out[b * NCLS + c] = sum * 0.25f + prodp;
}

// ---------------------------------------------------------------------------
extern "C" void kernel_launch(void* const* d_in, const int* in_sizes, int n_in,
                              void* d_out, int out_size)
{
    const float* questions = (const float*)d_in[0];
    const float* segments  = (const float*)d_in[1];
    const float* W1        = (const float*)d_in[2];
    const float* b1        = (const float*)d_in[3];
    const float* W2        = (const float*)d_in[4];
    const float* b2        = (const float*)d_in[5];
    const float* W3        = (const float*)d_in[6];
    const float* b3        = (const float*)d_in[7];
    const int*   nseg      = (const int*)d_in[8];
    float* out = (float*)d_out;

    float *pqW, *pH1, *pH2, *ppreds;
    cudaGetSymbolAddress((void**)&pqW,    g_qW);
    cudaGetSymbolAddress((void**)&pH1,    g_H1);
    cudaGetSymbolAddress((void**)&pH2,    g_H2);
    cudaGetSymbolAddress((void**)&ppreds, g_preds);

    // 1) qW[b] = q[b] @ W1[0:768] + b1          (128x768x768)
    gemm_tc<0><<<dim3(EDIM / 128, 1), 256>>>(
        questions, W1, pqW, b1, BATCH, EDIM, EDIM);

    // 2) H1 = gelu(seg @ W1[768:1536] + qW[b])  (32768x768x768)
    gemm_tc<1><<<dim3(EDIM / 128, NROWS / 128), 256>>>(
        segments, W1 + (size_t)EDIM * EDIM, pH1, pqW, NROWS, EDIM, EDIM);

    // 3) H2 = gelu(H1 @ W2 + b2)                (32768x384x768)
    gemm_tc<2><<<dim3(HDIM / 128, NROWS / 128), 256>>>(
        pH1, W2, pH2, b2, NROWS, HDIM, EDIM);

    // 4) preds = softmax(H2 @ W3 + b3)
    logits_softmax_k<<<(NROWS * 32) / 256, 256>>>(pH2, W3, b3, ppreds);

    // 5) per-bag aggregation
    aggregate_k<<<BATCH, 32>>>(ppreds, nseg, out);
}

// round 9
// speedup vs baseline: 3.7477x; 1.9520x over previous
#include <cuda_runtime.h>
#include <cuda_fp16.h>
#include <math.h>
#include <cstdint>

// Problem constants
#define EDIM   768
#define SDIM   256
#define BATCH  128
#define NROWS  (BATCH * SDIM)   // 32768
#define HDIM   (EDIM / 2)       // 384
#define NCLS   4

// Scratch (static device globals — no allocation APIs allowed)
__device__ float    g_qW[BATCH * EDIM];                     // q @ W1_top + b1 (fp32)
__device__ uint16_t g_H1h[(size_t)NROWS * EDIM];            // fp16, 50 MB
__device__ uint16_t g_H2h[(size_t)NROWS * HDIM];            // fp16, 25 MB
__device__ uint16_t g_W1T[(size_t)EDIM * EDIM];             // W1 bottom, transposed [N,K] fp16
__device__ uint16_t g_W2T[(size_t)HDIM * EDIM];             // W2 transposed [N,K] fp16
__device__ float    g_preds[NROWS * NCLS];

__device__ __forceinline__ float gelu_exact(float x) {
    return 0.5f * x * (1.0f + erff(x * 0.70710678118654752f));
}

// fp16 tensor-core mma: D[16x8] += A[16x16] * B[16x8], fp32 accumulate.
__device__ __forceinline__ void mma_f16(float* d, const uint32_t* a, const uint32_t* b) {
    asm volatile(
        "mma.sync.aligned.m16n8k16.row.col.f32.f16.f16.f32 "
        "{%0,%1,%2,%3}, {%4,%5,%6,%7}, {%8,%9}, {%0,%1,%2,%3};\n"
        : "+f"(d[0]), "+f"(d[1]), "+f"(d[2]), "+f"(d[3])
        : "r"(a[0]), "r"(a[1]), "r"(a[2]), "r"(a[3]), "r"(b[0]), "r"(b[1]));
}

// ---------------------------------------------------------------------------
// fp16 tensor-core GEMM: C[M,N](fp16) = epi(A[M,K] @ BT[N,K]^T)
// BM=BN=128, BK=32, 256 threads (8 warps, 2m x 4n), warp tile 64x32,
// mma m16n8k16, 4 mt x 4 nt per warp, 2 k-steps per BK chunk.
// Tiles stored as uint32 words (2 fp16/word), row stride 20 words
// (16 data + 4 pad) -> fragment loads conflict-free:
//   addr%32 = (gid*20 + tig) % 32, distinct for all 32 lanes.
// A: fp32 (AFP32=true, converted on fill) or fp16 (direct).
// BT: fp16 [N,K] K-major (pre-transposed weights).
// EPI 1: gelu(x + extra[(row>>8)*EDIM + col])   (qW add; fused question proj)
// EPI 2: gelu(x + extra[col])                   (bias add)
// All dims divide tiles exactly; no bounds checks.
// ---------------------------------------------------------------------------
template <bool AFP32, int EPI>
__global__ void __launch_bounds__(256) gemm_h(
    const void* __restrict__ Av, const uint16_t* __restrict__ BT,
    uint16_t* __restrict__ C, const float* __restrict__ extra,
    int M, int N, int K)
{
    constexpr int BM = 128, BN = 128, BK = 32;
    constexpr int STRIDE = BK / 2 + 4;              // 20 words per row
    __shared__ uint32_t As[BM * STRIDE];            // [m][k-pair]
    __shared__ uint32_t Bs[BN * STRIDE];            // [n][k-pair]

    const int bm = blockIdx.y * BM;
    const int bn = blockIdx.x * BN;
    const int tid = threadIdx.x, warp = tid >> 5, lane = tid & 31;
    const int gid = lane >> 2;            // 0..7
    const int tig = lane & 3;             // 0..3
    const int mwarp = (warp >> 2) * 64;   // 0 or 64
    const int nwarp = (warp & 3) * 32;    // 0,32,64,96

    float acc[4][4][4];
    #pragma unroll
    for (int mt = 0; mt < 4; mt++)
        #pragma unroll
        for (int nt = 0; nt < 4; nt++)
            #pragma unroll
            for (int r = 0; r < 4; r++) acc[mt][nt][r] = 0.0f;

    for (int k0 = 0; k0 < K; k0 += BK) {
        // ---- Fill A tile: 128 rows x 32 k ----
        if (AFP32) {
            const float* A = (const float*)Av;
            // 1024 float4 loads, 4 per thread
            #pragma unroll
            for (int i = 0; i < 4; i++) {
                int idx = tid + i * 256;
                int r = idx >> 3;              // 0..127
                int q = idx & 7;               // float4 group: cols q*4..q*4+3
                float4 v = *(const float4*)(A + (size_t)(bm + r) * K + k0 + q * 4);
                __half2 h0 = __floats2half2_rn(v.x, v.y);
                __half2 h1 = __floats2half2_rn(v.z, v.w);
                uint32_t* dst = &As[r * STRIDE + q * 2];
                dst[0] = *(uint32_t*)&h0;
                dst[1] = *(uint32_t*)&h1;
            }
        } else {
            const uint16_t* A = (const uint16_t*)Av;
            // 512 uint4 loads (8 halfs each), 2 per thread
            #pragma unroll
            for (int i = 0; i < 2; i++) {
                int idx = tid + i * 256;
                int r = idx >> 2;              // 0..127
                int q = idx & 3;               // 4-word group
                uint4 v = *(const uint4*)(A + (size_t)(bm + r) * K + k0 + q * 8);
                *(uint4*)&As[r * STRIDE + q * 4] = v;
            }
        }
        // ---- Fill B tile: 128 n-rows x 32 k ----
        #pragma unroll
        for (int i = 0; i < 2; i++) {
            int idx = tid + i * 256;
            int r = idx >> 2;
            int q = idx & 3;
            uint4 v = *(const uint4*)(BT + (size_t)(bn + r) * K + k0 + q * 8);
            *(uint4*)&Bs[r * STRIDE + q * 4] = v;
        }
        __syncthreads();

        #pragma unroll
        for (int ks = 0; ks < BK / 16; ks++) {
            const int kw = ks * 8;   // k-pair word offset (16 k = 8 words)
            uint32_t af[4][4];
            #pragma unroll
            for (int mt = 0; mt < 4; mt++) {
                int m = mwarp + mt * 16;
                const uint32_t* a0 = &As[(m + gid) * STRIDE + kw + tig];
                const uint32_t* a1 = &As[(m + gid + 8) * STRIDE + kw + tig];
                af[mt][0] = a0[0];
                af[mt][1] = a1[0];
                af[mt][2] = a0[4];
                af[mt][3] = a1[4];
            }
            uint32_t bf[4][2];
            #pragma unroll
            for (int nt = 0; nt < 4; nt++) {
                int n = nwarp + nt * 8;
                const uint32_t* b0 = &Bs[(n + gid) * STRIDE + kw + tig];
                bf[nt][0] = b0[0];
                bf[nt][1] = b0[4];
            }
            #pragma unroll
            for (int mt = 0; mt < 4; mt++)
                #pragma unroll
                for (int nt = 0; nt < 4; nt++)
                    mma_f16(acc[mt][nt], af[mt], bf[nt]);
        }
        __syncthreads();
    }

    // ---- Epilogue: c0,c1 @ (row gid, cols 2tig,2tig+1); c2,c3 @ row gid+8 ----
    #pragma unroll
    for (int mt = 0; mt < 4; mt++) {
        #pragma unroll
        for (int nt = 0; nt < 4; nt++) {
            int r0 = bm + mwarp + mt * 16 + gid;
            int r1 = r0 + 8;
            int c  = bn + nwarp + nt * 8 + 2 * tig;
            float v0 = acc[mt][nt][0], v1 = acc[mt][nt][1];
            float v2 = acc[mt][nt][2], v3 = acc[mt][nt][3];
            if (EPI == 1) {
                const float* ex0 = extra + (r0 >> 8) * EDIM;
                const float* ex1 = extra + (r1 >> 8) * EDIM;
                v0 = gelu_exact(v0 + ex0[c]); v1 = gelu_exact(v1 + ex0[c + 1]);
                v2 = gelu_exact(v2 + ex1[c]); v3 = gelu_exact(v3 + ex1[c + 1]);
            } else {
                float e0 = extra[c], e1 = extra[c + 1];
                v0 = gelu_exact(v0 + e0); v1 = gelu_exact(v1 + e1);
                v2 = gelu_exact(v2 + e0); v3 = gelu_exact(v3 + e1);
            }
            __half2 h01 = __floats2half2_rn(v0, v1);
            __half2 h23 = __floats2half2_rn(v2, v3);
            *(uint32_t*)(C + (size_t)r0 * N + c) = *(uint32_t*)&h01;
            *(uint32_t*)(C + (size_t)r1 * N + c) = *(uint32_t*)&h23;
        }
    }
}

// ======================= weight transpose + fp16 ============================
// dst[n*K + k] = fp16(src[k*N + n])
__global__ void transposeW_k(const float* __restrict__ src, uint16_t* __restrict__ dst,
                             int K, int N)
{
    int i = blockIdx.x * blockDim.x + threadIdx.x;
    if (i >= N * K) return;
    int n = i / K, k = i - n * K;
    __half h = __float2half(src[(size_t)k * N + n]);
    dst[i] = *(uint16_t*)&h;
}

// ======================= qW precompute (mma.sync tf32, small) ===============
__device__ __forceinline__ unsigned f2tf32(float x) {
    unsigned r;
    asm("cvt.rna.tf32.f32 %0, %1;" : "=r"(r) : "f"(x));
    return r;
}
__device__ __forceinline__ void mma_tf32(float* d, const unsigned* a, const unsigned* b) {
    asm volatile(
        "mma.sync.aligned.m16n8k8.row.col.f32.tf32.tf32.f32 "
        "{%0,%1,%2,%3}, {%4,%5,%6,%7}, {%8,%9}, {%0,%1,%2,%3};\n"
        : "+f"(d[0]), "+f"(d[1]), "+f"(d[2]), "+f"(d[3])
        : "r"(a[0]), "r"(a[1]), "r"(a[2]), "r"(a[3]), "r"(b[0]), "r"(b[1]));
}

__global__ void __launch_bounds__(256) qw_gemm_k(
    const float* __restrict__ A, const float* __restrict__ B,
    float* __restrict__ Cout, const float* __restrict__ bias,
    int M, int N, int K)
{
    constexpr int BM = 128, BN = 128, BK = 32;
    constexpr int APAD = 36, BPAD = 136;
    __shared__ unsigned As[BM * APAD];
    __shared__ unsigned Bs[BK * BPAD];

    const int bm = blockIdx.y * BM, bn = blockIdx.x * BN;
    const int tid = threadIdx.x, warp = tid >> 5, lane = tid & 31;
    const int gid = lane >> 2, tig = lane & 3;
    const int mwarp = (warp >> 2) * 64, nwarp = (warp & 3) * 32;

    float acc[4][4][4];
    #pragma unroll
    for (int mt = 0; mt < 4; mt++)
        #pragma unroll
        for (int nt = 0; nt < 4; nt++)
            #pragma unroll
            for (int r = 0; r < 4; r++) acc[mt][nt][r] = 0.0f;

    const float* Aptr = A + (size_t)bm * K;
    const float* Bptr = B + bn;
    for (int k0 = 0; k0 < K; k0 += BK) {
        #pragma unroll
        for (int i = 0; i < 4; i++) {
            int idx = tid + i * 256;
            int ar = idx >> 3, kq = (idx & 7) * 4;
            float4 v = *(const float4*)(Aptr + (size_t)ar * K + k0 + kq);
            unsigned* dst = &As[ar * APAD + kq];
            dst[0] = f2tf32(v.x); dst[1] = f2tf32(v.y);
            dst[2] = f2tf32(v.z); dst[3] = f2tf32(v.w);
        }
        #pragma unroll
        for (int i = 0; i < 4; i++) {
            int idx = tid + i * 256;
            int bk = idx >> 5, nq = (idx & 31) * 4;
            float4 v = *(const float4*)(Bptr + (size_t)(k0 + bk) * N + nq);
            unsigned* dst = &Bs[bk * BPAD + nq];
            dst[0] = f2tf32(v.x); dst[1] = f2tf32(v.y);
            dst[2] = f2tf32(v.z); dst[3] = f2tf32(v.w);
        }
        __syncthreads();
        #pragma unroll
        for (int ks = 0; ks < BK / 8; ks++) {
            const int k = ks * 8;
            unsigned af[4][4];
            #pragma unroll
            for (int mt = 0; mt < 4; mt++) {
                int m = mwarp + mt * 16;
                af[mt][0] = As[(m + gid)     * APAD + k + tig];
                af[mt][1] = As[(m + gid + 8) * APAD + k + tig];
                af[mt][2] = As[(m + gid)     * APAD + k + tig + 4];
                af[mt][3] = As[(m + gid + 8) * APAD + k + tig + 4];
            }
            unsigned bf[4][2];
            #pragma unroll
            for (int nt = 0; nt < 4; nt++) {
                int n = nwarp + nt * 8;
                bf[nt][0] = Bs[(k + tig)     * BPAD + n + gid];
                bf[nt][1] = Bs[(k + tig + 4) * BPAD + n + gid];
            }
            #pragma unroll
            for (int mt = 0; mt < 4; mt++)
                #pragma unroll
                for (int nt = 0; nt < 4; nt++)
                    mma_tf32(acc[mt][nt], af[mt], bf[nt]);
        }
        __syncthreads();
    }
    #pragma unroll
    for (int mt = 0; mt < 4; mt++)
        #pragma unroll
        for (int nt = 0; nt < 4; nt++) {
            int r0 = bm + mwarp + mt * 16 + gid;
            int r1 = r0 + 8;
            int c  = bn + nwarp + nt * 8 + 2 * tig;
            float e0 = bias[c], e1 = bias[c + 1];
            *(float2*)(Cout + (size_t)r0 * N + c) =
                make_float2(acc[mt][nt][0] + e0, acc[mt][nt][1] + e1);
            *(float2*)(Cout + (size_t)r1 * N + c) =
                make_float2(acc[mt][nt][2] + e0, acc[mt][nt][3] + e1);
        }
}

// ======================= logits + softmax (fp16 H2) =========================
__global__ void __launch_bounds__(256) logits_softmax_h(
    const uint16_t* __restrict__ H2h, const float* __restrict__ W3,
    const float* __restrict__ b3, float* __restrict__ preds)
{
    int warp = (blockIdx.x * blockDim.x + threadIdx.x) >> 5;
    int lane = threadIdx.x & 31;
    if (warp >= NROWS) return;

    const __half2* h2 = (const __half2*)(H2h + (size_t)warp * HDIM);
    float a0 = 0.f, a1 = 0.f, a2 = 0.f, a3 = 0.f;
    #pragma unroll
    for (int j = 0; j < HDIM / 64; j++) {
        int m = lane + j * 32;            // half2 index, cols 2m, 2m+1
        __half2 hv = h2[m];
        float x0 = __low2float(hv), x1 = __high2float(hv);
        float4 w0 = *(const float4*)(W3 + (2 * m) * 4);
        float4 w1 = *(const float4*)(W3 + (2 * m + 1) * 4);
        a0 = fmaf(x0, w0.x, fmaf(x1, w1.x, a0));
        a1 = fmaf(x0, w0.y, fmaf(x1, w1.y, a1));
        a2 = fmaf(x0, w0.z, fmaf(x1, w1.z, a2));
        a3 = fmaf(x0, w0.w, fmaf(x1, w1.w, a3));
    }
    #pragma unroll
    for (int off = 16; off; off >>= 1) {
        a0 += __shfl_xor_sync(0xffffffffu, a0, off);
        a1 += __shfl_xor_sync(0xffffffffu, a1, off);
        a2 += __shfl_xor_sync(0xffffffffu, a2, off);
        a3 += __shfl_xor_sync(0xffffffffu, a3, off);
    }
    if (lane == 0) {
        float l0 = a0 + b3[0], l1 = a1 + b3[1], l2 = a2 + b3[2], l3 = a3 + b3[3];
        float mx = fmaxf(fmaxf(l0, l1), fmaxf(l2, l3));
        float e0 = expf(l0 - mx), e1 = expf(l1 - mx), e2 = expf(l2 - mx), e3 = expf(l3 - mx);
        float inv = 1.0f / (e0 + e1 + e2 + e3);
        *(float4*)(preds + (size_t)warp * 4) =
            make_float4(e0 * inv, e1 * inv, e2 * inv, e3 * inv);
    }
}

// ======================= per-bag aggregation ================================
__global__ void aggregate_k(const float* __restrict__ preds,
                            const int* __restrict__ nseg,
                            float* __restrict__ out)
{
    int b = blockIdx.x;
    int c = threadIdx.x;
    __shared__ float ss[NCLS][SDIM];
    __shared__ float suf[NCLS][SDIM];
    if (c >= NCLS) return;

    int n = nseg[b];
    const float4* p = (const float4*)(preds + (size_t)b * SDIM * NCLS);

    for (int i = 0; i < n; i++) {
        float4 pv = p[i];
        float sv = (c == 0) ? 0.0f
                 : (c == 1) ? pv.x
                 : (c == 2) ? pv.x + pv.y
                            : pv.x + pv.y + pv.z;
        ss[c][i] = sv;
    }
    float r = 1.0f;
    for (int i = n - 1; i >= 0; i--) {
        suf[c][i] = r;
        r *= ss[c][i];
    }
    float pre = 1.0f, cpl = 1.0f, sum = 0.0f, prodp = 1.0f;
    for (int i = 0; i < n; i++) {
        float4 pv = p[i];
        float pc = (c == 0) ? pv.x : (c == 1) ? pv.y : (c == 2) ? pv.z : pv.w;
        float L = pre * suf[c][i];
        cpl *= L;
        sum = fmaf(pc, cpl, sum);
        prodp *= pc;
        pre *= ss[c][i];
    }
    out[b * NCLS + c] = sum * 0.25f + prodp;
}

// ===========================================================================
extern "C" void kernel_launch(void* const* d_in, const int* in_sizes, int n_in,
                              void* d_out, int out_size)
{
    const float* questions = (const float*)d_in[0];
    const float* segments  = (const float*)d_in[1];
    const float* W1        = (const float*)d_in[2];
    const float* b1        = (const float*)d_in[3];
    const float* W2        = (const float*)d_in[4];
    const float* b2        = (const float*)d_in[5];
    const float* W3        = (const float*)d_in[6];
    const float* b3        = (const float*)d_in[7];
    const int*   nseg      = (const int*)d_in[8];
    float* out = (float*)d_out;

    float *pqW, *ppreds;
    uint16_t *pH1h, *pH2h, *pW1T, *pW2T;
    cudaGetSymbolAddress((void**)&pqW,    g_qW);
    cudaGetSymbolAddress((void**)&pH1h,   g_H1h);
    cudaGetSymbolAddress((void**)&pH2h,   g_H2h);
    cudaGetSymbolAddress((void**)&pW1T,   g_W1T);
    cudaGetSymbolAddress((void**)&pW2T,   g_W2T);
    cudaGetSymbolAddress((void**)&ppreds, g_preds);

    // 0) weight transpose + fp16 convert
    transposeW_k<<<(EDIM * EDIM + 255) / 256, 256>>>(W1 + (size_t)EDIM * EDIM, pW1T, EDIM, EDIM);
    transposeW_k<<<(HDIM * EDIM + 255) / 256, 256>>>(W2, pW2T, EDIM, HDIM);

    // 1) qW[b] = q[b] @ W1_top + b1   (128 x 768 x 768, tf32 — fp32 inputs kept exact-ish)
    qw_gemm_k<<<dim3(EDIM / 128, 1), 256>>>(questions, W1, pqW, b1, BATCH, EDIM, EDIM);

    // 2) H1h = gelu(seg @ W1_botT^T + qW[b])   (fp16 mma, 32768 x 768 x 768)
    gemm_h<true, 1><<<dim3(EDIM / 128, NROWS / 128), 256>>>(
        segments, pW1T, pH1h, pqW, NROWS, EDIM, EDIM);

    // 3) H2h = gelu(H1h @ W2T^T + b2)          (fp16 mma, 32768 x 384 x 768)
    gemm_h<false, 2><<<dim3(HDIM / 128, NROWS / 128), 256>>>(
        pH1h, pW2T, pH2h, b2, NROWS, HDIM, EDIM);

    // 4) preds = softmax(H2h @ W3 + b3)
    logits_softmax_h<<<(NROWS * 32) / 256, 256>>>(pH2h, W3, b3, ppreds);

    // 5) per-bag aggregation
    aggregate_k<<<BATCH, 32>>>(ppreds, nseg, out);
}

// round 10
// speedup vs baseline: 4.8097x; 1.2834x over previous
#include <cuda_runtime.h>
#include <cuda_fp16.h>
#include <math.h>
#include <cstdint>

// Problem constants
#define EDIM   768
#define SDIM   256
#define BATCH  128
#define NROWS  (BATCH * SDIM)   // 32768
#define HDIM   (EDIM / 2)       // 384
#define NCLS   4

// Scratch (static device globals — no allocation APIs allowed)
__device__ float    g_qW[BATCH * EDIM];                     // q @ W1_top + b1 (fp32)
__device__ uint16_t g_segh[(size_t)NROWS * EDIM];           // segments fp16, 50 MB
__device__ uint16_t g_H1h[(size_t)NROWS * EDIM];            // fp16, 50 MB
__device__ uint16_t g_H2h[(size_t)NROWS * HDIM];            // fp16, 25 MB
__device__ uint16_t g_W1T[(size_t)EDIM * EDIM];             // W1 bottom, transposed [N,K] fp16
__device__ uint16_t g_W2T[(size_t)HDIM * EDIM];             // W2 transposed [N,K] fp16
__device__ float    g_preds[NROWS * NCLS];

__device__ __forceinline__ float gelu_exact(float x) {
    return 0.5f * x * (1.0f + erff(x * 0.70710678118654752f));
}

__device__ __forceinline__ uint32_t smem_u32(const void* p) {
    uint32_t a;
    asm("{ .reg .u64 t; cvta.to.shared.u64 t, %1; cvt.u32.u64 %0, t; }" : "=r"(a) : "l"(p));
    return a;
}
__device__ __forceinline__ void cp16(uint32_t saddr, const void* g) {
    asm volatile("cp.async.cg.shared.global [%0], [%1], 16;" :: "r"(saddr), "l"(g));
}
#define CP_COMMIT() asm volatile("cp.async.commit_group;" ::: "memory")
#define CP_WAIT0()  asm volatile("cp.async.wait_group 0;"  ::: "memory")

__device__ __forceinline__ void ldsm_x4(uint32_t* r, uint32_t addr) {
    asm volatile("ldmatrix.sync.aligned.m8n8.x4.shared.b16 {%0,%1,%2,%3}, [%4];"
                 : "=r"(r[0]), "=r"(r[1]), "=r"(r[2]), "=r"(r[3]) : "r"(addr));
}
// fp16 tensor-core mma: D[16x8] += A[16x16] * B[16x8], fp32 accumulate.
__device__ __forceinline__ void mma_f16(float* d, const uint32_t* a, const uint32_t* b) {
    asm volatile(
        "mma.sync.aligned.m16n8k16.row.col.f32.f16.f16.f32 "
        "{%0,%1,%2,%3}, {%4,%5,%6,%7}, {%8,%9}, {%0,%1,%2,%3};\n"
        : "+f"(d[0]), "+f"(d[1]), "+f"(d[2]), "+f"(d[3])
        : "r"(a[0]), "r"(a[1]), "r"(a[2]), "r"(a[3]), "r"(b[0]), "r"(b[1]));
}

// ---------------------------------------------------------------------------
// fp16 tensor-core GEMM, cp.async double-buffered + ldmatrix fragments.
// C[M,N](fp16) = epi(A[M,K] @ BT[N,K]^T); BM=BN=128, BK=32, 8 warps (2m x 4n),
// warp tile 64x32, mma m16n8k16. Tile rows: 16 data words + 4 pad = 20 words
// (LDSM 8-row x 16B reads hit all 32 banks exactly once -> conflict-free).
// EPI 1: gelu(x + extra[(row>>8)*EDIM + col])   (qW add)
// EPI 2: gelu(x + extra[col])                   (bias add)
// All dims divide tiles exactly; no bounds checks.
// ---------------------------------------------------------------------------
template <int EPI>
__global__ void __launch_bounds__(256, 2) gemm_h(
    const uint16_t* __restrict__ A, const uint16_t* __restrict__ BT,
    uint16_t* __restrict__ C, const float* __restrict__ extra,
    int M, int N, int K)
{
    constexpr int BM = 128, BN = 128, BK = 32;
    constexpr int STRIDE = BK / 2 + 4;                 // 20 words/row
    constexpr int BUFW = BM * STRIDE;                  // 2560 words = 10240 B
    __shared__ uint32_t As[2][BUFW];
    __shared__ uint32_t Bs[2][BUFW];

    const int bm = blockIdx.y * BM;
    const int bn = blockIdx.x * BN;
    const int tid = threadIdx.x, warp = tid >> 5, lane = tid & 31;
    const int gid = lane >> 2;            // 0..7
    const int tig = lane & 3;             // 0..3
    const int mwarp = (warp >> 2) * 64;   // 0 or 64
    const int nwarp = (warp & 3) * 32;    // 0,32,64,96

    const uint32_t asA = smem_u32(As);
    const uint32_t asB = smem_u32(Bs);

    // Per-chunk fill: 2 cp16 into A + 2 into B per thread (512 x 16B each tile)
    const int fr = tid >> 2;              // 0..63  (row pair base; two passes)
    const int fq = tid & 3;               // 16B group in row
    const uint16_t* Abase = A + (size_t)bm * K;
    const uint16_t* Bbase = BT + (size_t)bn * K;

    // ldmatrix per-lane addresses (byte offsets inside a buffer)
    const uint32_t a_off = ((mwarp + (lane & 15)) * STRIDE + ((lane & 16) ? 4 : 0)) * 4;
    const uint32_t b_off = ((nwarp + ((lane & 16) ? 8 : 0) + (lane & 7)) * STRIDE
                            + ((lane & 8) ? 4 : 0)) * 4;

    float acc[4][4][4];
    #pragma unroll
    for (int mt = 0; mt < 4; mt++)
        #pragma unroll
        for (int nt = 0; nt < 4; nt++)
            #pragma unroll
            for (int r = 0; r < 4; r++) acc[mt][nt][r] = 0.0f;

    const int nkc = K / BK;

    // prologue: load chunk 0 into buf 0
    {
        const uint16_t* Ab = Abase;                    // k0 = 0
        const uint16_t* Bb = Bbase;
        #pragma unroll
        for (int i = 0; i < 2; i++) {
            int r = fr + i * 64;
            uint32_t d = (r * STRIDE + fq * 4) * 4;
            cp16(asA + d, Ab + (size_t)r * K + fq * 8);
            cp16(asB + d, Bb + (size_t)r * K + fq * 8);
        }
    }
    CP_COMMIT();

    int buf = 0;
    for (int kc = 0; kc < nkc; kc++) {
        CP_WAIT0();
        __syncthreads();     // chunk kc visible; all warps done with buf^1 compute

        if (kc + 1 < nkc) {
            const uint16_t* Ab = Abase + (kc + 1) * BK;
            const uint16_t* Bb = Bbase + (kc + 1) * BK;
            uint32_t bofs = (buf ^ 1) * (BUFW * 4);
            #pragma unroll
            for (int i = 0; i < 2; i++) {
                int r = fr + i * 64;
                uint32_t d = bofs + (r * STRIDE + fq * 4) * 4;
                cp16(asA + d, Ab + (size_t)r * K + fq * 8);
                cp16(asB + d, Bb + (size_t)r * K + fq * 8);
            }
        }
        CP_COMMIT();

        const uint32_t abase = asA + buf * (BUFW * 4) + a_off;
        const uint32_t bbase = asB + buf * (BUFW * 4) + b_off;
        #pragma unroll
        for (int ks = 0; ks < 2; ks++) {
            uint32_t af[4][4];
            #pragma unroll
            for (int mt = 0; mt < 4; mt++)
                ldsm_x4(af[mt], abase + mt * (16 * STRIDE * 4) + ks * 32);
            uint32_t bf[4][2];
            ldsm_x4(&bf[0][0], bbase + ks * 32);                       // nt0, nt1
            ldsm_x4(&bf[2][0], bbase + 16 * STRIDE * 4 + ks * 32);     // nt2, nt3
            #pragma unroll
            for (int mt = 0; mt < 4; mt++)
                #pragma unroll
                for (int nt = 0; nt < 4; nt++)
                    mma_f16(acc[mt][nt], af[mt], bf[nt]);
        }
        buf ^= 1;
    }

    // ---- Epilogue: c0,c1 @ (row gid, cols 2tig,2tig+1); c2,c3 @ row gid+8 ----
    #pragma unroll
    for (int mt = 0; mt < 4; mt++) {
        #pragma unroll
        for (int nt = 0; nt < 4; nt++) {
            int r0 = bm + mwarp + mt * 16 + gid;
            int r1 = r0 + 8;
            int c  = bn + nwarp + nt * 8 + 2 * tig;
            float v0 = acc[mt][nt][0], v1 = acc[mt][nt][1];
            float v2 = acc[mt][nt][2], v3 = acc[mt][nt][3];
            if (EPI == 1) {
                const float* ex0 = extra + (r0 >> 8) * EDIM;
                const float* ex1 = extra + (r1 >> 8) * EDIM;
                v0 = gelu_exact(v0 + ex0[c]); v1 = gelu_exact(v1 + ex0[c + 1]);
                v2 = gelu_exact(v2 + ex1[c]); v3 = gelu_exact(v3 + ex1[c + 1]);
            } else {
                float e0 = extra[c], e1 = extra[c + 1];
                v0 = gelu_exact(v0 + e0); v1 = gelu_exact(v1 + e1);
                v2 = gelu_exact(v2 + e0); v3 = gelu_exact(v3 + e1);
            }
            __half2 h01 = __floats2half2_rn(v0, v1);
            __half2 h23 = __floats2half2_rn(v2, v3);
            *(uint32_t*)(C + (size_t)r0 * N + c) = *(uint32_t*)&h01;
            *(uint32_t*)(C + (size_t)r1 * N + c) = *(uint32_t*)&h23;
        }
    }
}

// ======================= fp32 -> fp16 bulk convert ==========================
__global__ void f2h_k(const float* __restrict__ src, uint16_t* __restrict__ dst, int n4)
{
    int i = blockIdx.x * blockDim.x + threadIdx.x;
    if (i >= n4) return;
    float4 v = ((const float4*)src)[i];
    __half2 h0 = __floats2half2_rn(v.x, v.y);
    __half2 h1 = __floats2half2_rn(v.z, v.w);
    ((uint2*)dst)[i] = make_uint2(*(uint32_t*)&h0, *(uint32_t*)&h1);
}

// ======================= tiled weight transpose + fp16 ======================
// dst[n*K + k] = fp16(src[k*N + n]); 32x32 smem tiles, 256 threads.
__global__ void transposeW_t(const float* __restrict__ src, uint16_t* __restrict__ dst,
                             int K, int N)
{
    __shared__ float t[32][33];
    int n0 = blockIdx.x * 32, k0 = blockIdx.y * 32;
    int tx = threadIdx.x & 31, ty = threadIdx.x >> 5;   // ty 0..7
    #pragma unroll
    for (int j = 0; j < 32; j += 8)
        t[ty + j][tx] = src[(size_t)(k0 + ty + j) * N + n0 + tx];
    __syncthreads();
    #pragma unroll
    for (int j = 0; j < 32; j += 8) {
        __half h = __float2half(t[tx][ty + j]);
        dst[(size_t)(n0 + ty + j) * K + k0 + tx] = *(uint16_t*)&h;
    }
}

// ======================= qW precompute (mma.sync tf32, small) ===============
__device__ __forceinline__ unsigned f2tf32(float x) {
    unsigned r;
    asm("cvt.rna.tf32.f32 %0, %1;" : "=r"(r) : "f"(x));
    return r;
}
__device__ __forceinline__ void mma_tf32(float* d, const unsigned* a, const unsigned* b) {
    asm volatile(
        "mma.sync.aligned.m16n8k8.row.col.f32.tf32.tf32.f32 "
        "{%0,%1,%2,%3}, {%4,%5,%6,%7}, {%8,%9}, {%0,%1,%2,%3};\n"
        : "+f"(d[0]), "+f"(d[1]), "+f"(d[2]), "+f"(d[3])
        : "r"(a[0]), "r"(a[1]), "r"(a[2]), "r"(a[3]), "r"(b[0]), "r"(b[1]));
}

__global__ void __launch_bounds__(256) qw_gemm_k(
    const float* __restrict__ A, const float* __restrict__ B,
    float* __restrict__ Cout, const float* __restrict__ bias,
    int M, int N, int K)
{
    constexpr int BM = 128, BN = 128, BK = 32;
    constexpr int APAD = 36, BPAD = 136;
    __shared__ unsigned As[BM * APAD];
    __shared__ unsigned Bs[BK * BPAD];

    const int bm = blockIdx.y * BM, bn = blockIdx.x * BN;
    const int tid = threadIdx.x, warp = tid >> 5, lane = tid & 31;
    const int gid = lane >> 2, tig = lane & 3;
    const int mwarp = (warp >> 2) * 64, nwarp = (warp & 3) * 32;

    float acc[4][4][4];
    #pragma unroll
    for (int mt = 0; mt < 4; mt++)
        #pragma unroll
        for (int nt = 0; nt < 4; nt++)
            #pragma unroll
            for (int r = 0; r < 4; r++) acc[mt][nt][r] = 0.0f;

    const float* Aptr = A + (size_t)bm * K;
    const float* Bptr = B + bn;
    for (int k0 = 0; k0 < K; k0 += BK) {
        #pragma unroll
        for (int i = 0; i < 4; i++) {
            int idx = tid + i * 256;
            int ar = idx >> 3, kq = (idx & 7) * 4;
            float4 v = *(const float4*)(Aptr + (size_t)ar * K + k0 + kq);
            unsigned* dst = &As[ar * APAD + kq];
            dst[0] = f2tf32(v.x); dst[1] = f2tf32(v.y);
            dst[2] = f2tf32(v.z); dst[3] = f2tf32(v.w);
        }
        #pragma unroll
        for (int i = 0; i < 4; i++) {
            int idx = tid + i * 256;
            int bk = idx >> 5, nq = (idx & 31) * 4;
            float4 v = *(const float4*)(Bptr + (size_t)(k0 + bk) * N + nq);
            unsigned* dst = &Bs[bk * BPAD + nq];
            dst[0] = f2tf32(v.x); dst[1] = f2tf32(v.y);
            dst[2] = f2tf32(v.z); dst[3] = f2tf32(v.w);
        }
        __syncthreads();
        #pragma unroll
        for (int ks = 0; ks < BK / 8; ks++) {
            const int k = ks * 8;
            unsigned af[4][4];
            #pragma unroll
            for (int mt = 0; mt < 4; mt++) {
                int m = mwarp + mt * 16;
                af[mt][0] = As[(m + gid)     * APAD + k + tig];
                af[mt][1] = As[(m + gid + 8) * APAD + k + tig];
                af[mt][2] = As[(m + gid)     * APAD + k + tig + 4];
                af[mt][3] = As[(m + gid + 8) * APAD + k + tig + 4];
            }
            unsigned bf[4][2];
            #pragma unroll
            for (int nt = 0; nt < 4; nt++) {
                int n = nwarp + nt * 8;
                bf[nt][0] = Bs[(k + tig)     * BPAD + n + gid];
                bf[nt][1] = Bs[(k + tig + 4) * BPAD + n + gid];
            }
            #pragma unroll
            for (int mt = 0; mt < 4; mt++)
                #pragma unroll
                for (int nt = 0; nt < 4; nt++)
                    mma_tf32(acc[mt][nt], af[mt], bf[nt]);
        }
        __syncthreads();
    }
    #pragma unroll
    for (int mt = 0; mt < 4; mt++)
        #pragma unroll
        for (int nt = 0; nt < 4; nt++) {
            int r0 = bm + mwarp + mt * 16 + gid;
            int r1 = r0 + 8;
            int c  = bn + nwarp + nt * 8 + 2 * tig;
            float e0 = bias[c], e1 = bias[c + 1];
            *(float2*)(Cout + (size_t)r0 * N + c) =
                make_float2(acc[mt][nt][0] + e0, acc[mt][nt][1] + e1);
            *(float2*)(Cout + (size_t)r1 * N + c) =
                make_float2(acc[mt][nt][2] + e0, acc[mt][nt][3] + e1);
        }
}

// ======================= logits + softmax (fp16 H2) =========================
__global__ void __launch_bounds__(256) logits_softmax_h(
    const uint16_t* __restrict__ H2h, const float* __restrict__ W3,
    const float* __restrict__ b3, float* __restrict__ preds)
{
    int warp = (blockIdx.x * blockDim.x + threadIdx.x) >> 5;
    int lane = threadIdx.x & 31;
    if (warp >= NROWS) return;

    const __half2* h2 = (const __half2*)(H2h + (size_t)warp * HDIM);
    float a0 = 0.f, a1 = 0.f, a2 = 0.f, a3 = 0.f;
    #pragma unroll
    for (int j = 0; j < HDIM / 64; j++) {
        int m = lane + j * 32;            // half2 index, cols 2m, 2m+1
        __half2 hv = h2[m];
        float x0 = __low2float(hv), x1 = __high2float(hv);
        float4 w0 = *(const float4*)(W3 + (2 * m) * 4);
        float4 w1 = *(const float4*)(W3 + (2 * m + 1) * 4);
        a0 = fmaf(x0, w0.x, fmaf(x1, w1.x, a0));
        a1 = fmaf(x0, w0.y, fmaf(x1, w1.y, a1));
        a2 = fmaf(x0, w0.z, fmaf(x1, w1.z, a2));
        a3 = fmaf(x0, w0.w, fmaf(x1, w1.w, a3));
    }
    #pragma unroll
    for (int off = 16; off; off >>= 1) {
        a0 += __shfl_xor_sync(0xffffffffu, a0, off);
        a1 += __shfl_xor_sync(0xffffffffu, a1, off);
        a2 += __shfl_xor_sync(0xffffffffu, a2, off);
        a3 += __shfl_xor_sync(0xffffffffu, a3, off);
    }
    if (lane == 0) {
        float l0 = a0 + b3[0], l1 = a1 + b3[1], l2 = a2 + b3[2], l3 = a3 + b3[3];
        float mx = fmaxf(fmaxf(l0, l1), fmaxf(l2, l3));
        float e0 = expf(l0 - mx), e1 = expf(l1 - mx), e2 = expf(l2 - mx), e3 = expf(l3 - mx);
        float inv = 1.0f / (e0 + e1 + e2 + e3);
        *(float4*)(preds + (size_t)warp * 4) =
            make_float4(e0 * inv, e1 * inv, e2 * inv, e3 * inv);
    }
}

// ======================= per-bag aggregation ================================
__global__ void aggregate_k(const float* __restrict__ preds,
                            const int* __restrict__ nseg,
                            float* __restrict__ out)
{
    int b = blockIdx.x;
    int c = threadIdx.x;
    __shared__ float ss[NCLS][SDIM];
    __shared__ float suf[NCLS][SDIM];
    if (c >= NCLS) return;

    int n = nseg[b];
    const float4* p = (const float4*)(preds + (size_t)b * SDIM * NCLS);

    for (int i = 0; i < n; i++) {
        float4 pv = p[i];
        float sv = (c == 0) ? 0.0f
                 : (c == 1) ? pv.x
                 : (c == 2) ? pv.x + pv.y
                            : pv.x + pv.y + pv.z;
        ss[c][i] = sv;
    }
    float r = 1.0f;
    for (int i = n - 1; i >= 0; i--) {
        suf[c][i] = r;
        r *= ss[c][i];
    }
    float pre = 1.0f, cpl = 1.0f, sum = 0.0f, prodp = 1.0f;
    for (int i = 0; i < n; i++) {
        float4 pv = p[i];
        float pc = (c == 0) ? pv.x : (c == 1) ? pv.y : (c == 2) ? pv.z : pv.w;
        float L = pre * suf[c][i];
        cpl *= L;
        sum = fmaf(pc, cpl, sum);
        prodp *= pc;
        pre *= ss[c][i];
    }
    out[b * NCLS + c] = sum * 0.25f + prodp;
}

// ===========================================================================
extern "C" void kernel_launch(void* const* d_in, const int* in_sizes, int n_in,
                              void* d_out, int out_size)
{
    const float* questions = (const float*)d_in[0];
    const float* segments  = (const float*)d_in[1];
    const float* W1        = (const float*)d_in[2];
    const float* b1        = (const float*)d_in[3];
    const float* W2        = (const float*)d_in[4];
    const float* b2        = (const float*)d_in[5];
    const float* W3        = (const float*)d_in[6];
    const float* b3        = (const float*)d_in[7];
    const int*   nseg      = (const int*)d_in[8];
    float* out = (float*)d_out;

    float *pqW, *ppreds;
    uint16_t *psegh, *pH1h, *pH2h, *pW1T, *pW2T;
    cudaGetSymbolAddress((void**)&pqW,    g_qW);
    cudaGetSymbolAddress((void**)&psegh,  g_segh);
    cudaGetSymbolAddress((void**)&pH1h,   g_H1h);
    cudaGetSymbolAddress((void**)&pH2h,   g_H2h);
    cudaGetSymbolAddress((void**)&pW1T,   g_W1T);
    cudaGetSymbolAddress((void**)&pW2T,   g_W2T);
    cudaGetSymbolAddress((void**)&ppreds, g_preds);

    // 0a) segments -> fp16
    f2h_k<<<((size_t)NROWS * EDIM / 4 + 255) / 256, 256>>>(
        segments, psegh, NROWS * EDIM / 4);
    // 0b) weight transpose + fp16 convert (tiled)
    transposeW_t<<<dim3(EDIM / 32, EDIM / 32), 256>>>(W1 + (size_t)EDIM * EDIM, pW1T, EDIM, EDIM);
    transposeW_t<<<dim3(HDIM / 32, EDIM / 32), 256>>>(W2, pW2T, EDIM, HDIM);

    // 1) qW[b] = q[b] @ W1_top + b1   (128 x 768 x 768, tf32)
    qw_gemm_k<<<dim3(EDIM / 128, 1), 256>>>(questions, W1, pqW, b1, BATCH, EDIM, EDIM);

    // 2) H1h = gelu(seg @ W1_botT^T + qW[b])   (fp16 mma pipelined)
    gemm_h<1><<<dim3(EDIM / 128, NROWS / 128), 256>>>(
        psegh, pW1T, pH1h, pqW, NROWS, EDIM, EDIM);

    // 3) H2h = gelu(H1h @ W2T^T + b2)
    gemm_h<2><<<dim3(HDIM / 128, NROWS / 128), 256>>>(
        pH1h, pW2T, pH2h, b2, NROWS, HDIM, EDIM);

    // 4) preds = softmax(H2h @ W3 + b3)
    logits_softmax_h<<<(NROWS * 32) / 256, 256>>>(pH2h, W3, b3, ppreds);

    // 5) per-bag aggregation
    aggregate_k<<<BATCH, 32>>>(ppreds, nseg, out);
}

// round 13
// speedup vs baseline: 5.3254x; 1.1072x over previous
#include <cuda_runtime.h>
#include <cuda_fp16.h>
#include <math.h>
#include <cstdint>

// Problem constants
#define EDIM   768
#define SDIM   256
#define BATCH  128
#define NROWS  (BATCH * SDIM)   // 32768
#define HDIM   (EDIM / 2)       // 384
#define NCLS   4
#define QW_SLICES 6
#define QW_ELEMS  (BATCH * EDIM)

// Scratch (static device globals — no allocation APIs allowed)
__device__ float    g_qW[QW_ELEMS];                         // q @ W1_top + b1 (fp32)
__device__ float    g_qWpart[QW_SLICES * QW_ELEMS];         // split-K partials
__device__ uint16_t g_segh[(size_t)NROWS * EDIM];           // segments fp16, 50 MB
__device__ uint16_t g_H1h[(size_t)NROWS * EDIM];            // fp16, 50 MB
__device__ uint16_t g_H2h[(size_t)NROWS * HDIM];            // fp16, 25 MB
__device__ uint16_t g_W1T[(size_t)EDIM * EDIM];             // W1 bottom, transposed [N,K] fp16
__device__ uint16_t g_W2T[(size_t)HDIM * EDIM];             // W2 transposed [N,K] fp16
__device__ float    g_preds[NROWS * NCLS];

__device__ __forceinline__ float gelu_exact(float x) {
    return 0.5f * x * (1.0f + erff(x * 0.70710678118654752f));
}

__device__ __forceinline__ uint32_t smem_u32(const void* p) {
    uint32_t a;
    asm("{ .reg .u64 t; cvta.to.shared.u64 t, %1; cvt.u32.u64 %0, t; }" : "=r"(a) : "l"(p));
    return a;
}
__device__ __forceinline__ void cp16(uint32_t saddr, const void* g) {
    asm volatile("cp.async.cg.shared.global [%0], [%1], 16;" :: "r"(saddr), "l"(g));
}
#define CP_COMMIT() asm volatile("cp.async.commit_group;" ::: "memory")
#define CP_WAIT1()  asm volatile("cp.async.wait_group 1;"  ::: "memory")

__device__ __forceinline__ void ldsm_x4(uint32_t* r, uint32_t addr) {
    asm volatile("ldmatrix.sync.aligned.m8n8.x4.shared.b16 {%0,%1,%2,%3}, [%4];"
                 : "=r"(r[0]), "=r"(r[1]), "=r"(r[2]), "=r"(r[3]) : "r"(addr));
}
// fp16 tensor-core mma: D[16x8] += A[16x16] * B[16x8], fp32 accumulate.
__device__ __forceinline__ void mma_f16(float* d, const uint32_t* a, const uint32_t* b) {
    asm volatile(
        "mma.sync.aligned.m16n8k16.row.col.f32.f16.f16.f32 "
        "{%0,%1,%2,%3}, {%4,%5,%6,%7}, {%8,%9}, {%0,%1,%2,%3};\n"
        : "+f"(d[0]), "+f"(d[1]), "+f"(d[2]), "+f"(d[3])
        : "r"(a[0]), "r"(a[1]), "r"(a[2]), "r"(a[3]), "r"(b[0]), "r"(b[1]));
}

// ---------------------------------------------------------------------------
// fp16 tensor-core GEMM, 3-stage cp.async pipeline + ldmatrix fragments.
// C[M,N](fp16) = epi(A[M,K] @ BT[N,K]^T); BM=BN=128, BK=32, 8 warps (2m x 4n),
// warp tile 64x32, mma m16n8k16. Tile rows: 16 data words + 4 pad = 20 words
// (LDSM 8-row x 16B reads hit all 32 banks exactly once -> conflict-free).
// Dynamic smem: 3 stages x (A 10240 B + B 10240 B) = 61440 B.
// EPI 1: gelu(x + extra[(row>>8)*EDIM + col])   (qW add)
// EPI 2: gelu(x + extra[col])                   (bias add)
// All dims divide tiles exactly; no bounds checks. K/32 >= 3 assumed.
// ---------------------------------------------------------------------------
template <int EPI>
__global__ void __launch_bounds__(256, 2) gemm_h(
    const uint16_t* __restrict__ A, const uint16_t* __restrict__ BT,
    uint16_t* __restrict__ C, const float* __restrict__ extra,
    int M, int N, int K)
{
    constexpr int BM = 128, BK = 32;
    constexpr int STRIDE = BK / 2 + 4;                 // 20 words/row
    constexpr int TILEB = BM * STRIDE * 4;             // 10240 bytes per tile
    constexpr int STAGEB = 2 * TILEB;                  // 20480 bytes per stage
    extern __shared__ uint32_t smem[];

    const int bm = blockIdx.y * BM;
    const int bn = blockIdx.x * BM;
    const int tid = threadIdx.x, warp = tid >> 5, lane = tid & 31;
    const int gid = lane >> 2;            // 0..7
    const int tig = lane & 3;             // 0..3
    const int mwarp = (warp >> 2) * 64;   // 0 or 64
    const int nwarp = (warp & 3) * 32;    // 0,32,64,96

    const uint32_t sb = smem_u32(smem);

    // Per-chunk fill: 2 cp16 into A + 2 into B per thread (512 x 16B each tile)
    const int fr = tid >> 2;              // 0..63
    const int fq = tid & 3;               // 16B group in row
    const uint16_t* Abase = A + (size_t)bm * K;
    const uint16_t* Bbase = BT + (size_t)bn * K;

    // ldmatrix per-lane byte offsets (within a stage)
    const uint32_t a_off = ((mwarp + (lane & 15)) * STRIDE + ((lane & 16) ? 4 : 0)) * 4;
    const uint32_t b_off = TILEB + ((nwarp + ((lane & 16) ? 8 : 0) + (lane & 7)) * STRIDE
                            + ((lane & 8) ? 4 : 0)) * 4;

    float acc[4][4][4];
    #pragma unroll
    for (int mt = 0; mt < 4; mt++)
        #pragma unroll
        for (int nt = 0; nt < 4; nt++)
            #pragma unroll
            for (int r = 0; r < 4; r++) acc[mt][nt][r] = 0.0f;

    const int nkc = K / BK;

    // prologue: chunks 0,1 into stages 0,1
    #pragma unroll
    for (int pc = 0; pc < 2; pc++) {
        const uint16_t* Ab = Abase + pc * BK;
        const uint16_t* Bb = Bbase + pc * BK;
        uint32_t st = sb + pc * STAGEB;
        #pragma unroll
        for (int i = 0; i < 2; i++) {
            int r = fr + i * 64;
            uint32_t d = (r * STRIDE + fq * 4) * 4;
            cp16(st + d, Ab + (size_t)r * K + fq * 8);
            cp16(st + TILEB + d, Bb + (size_t)r * K + fq * 8);
        }
        CP_COMMIT();
    }

    int s = 0;   // stage of current chunk
    for (int kc = 0; kc < nkc; kc++) {
        CP_WAIT1();          // chunk kc landed (only kc+1 may remain in flight)
        __syncthreads();     // all warps done computing chunk kc-1 (stage being refilled)

        if (kc + 2 < nkc) {
            const uint16_t* Ab = Abase + (kc + 2) * BK;
            const uint16_t* Bb = Bbase + (kc + 2) * BK;
            int sn = s + 2; if (sn >= 3) sn -= 3;
            uint32_t st = sb + sn * STAGEB;
            #pragma unroll
            for (int i = 0; i < 2; i++) {
                int r = fr + i * 64;
                uint32_t d = (r * STRIDE + fq * 4) * 4;
                cp16(st + d, Ab + (size_t)r * K + fq * 8);
                cp16(st + TILEB + d, Bb + (size_t)r * K + fq * 8);
            }
        }
        CP_COMMIT();         // commit every iteration (possibly empty group)

        const uint32_t abase = sb + s * STAGEB + a_off;
        const uint32_t bbase = sb + s * STAGEB + b_off;
        #pragma unroll
        for (int ks = 0; ks < 2; ks++) {
            uint32_t af[4][4];
            #pragma unroll
            for (int mt = 0; mt < 4; mt++)
                ldsm_x4(af[mt], abase + mt * (16 * STRIDE * 4) + ks * 32);
            uint32_t bf[4][2];
            ldsm_x4(&bf[0][0], bbase + ks * 32);                       // nt0, nt1
            ldsm_x4(&bf[2][0], bbase + 16 * STRIDE * 4 + ks * 32);     // nt2, nt3
            #pragma unroll
            for (int mt = 0; mt < 4; mt++)
                #pragma unroll
                for (int nt = 0; nt < 4; nt++)
                    mma_f16(acc[mt][nt], af[mt], bf[nt]);
        }
        if (++s == 3) s = 0;
    }

    // ---- Epilogue: c0,c1 @ (row gid, cols 2tig,2tig+1); c2,c3 @ row gid+8 ----
    #pragma unroll
    for (int mt = 0; mt < 4; mt++) {
        #pragma unroll
        for (int nt = 0; nt < 4; nt++) {
            int r0 = bm + mwarp + mt * 16 + gid;
            int r1 = r0 + 8;
            int c  = bn + nwarp + nt * 8 + 2 * tig;
            float v0 = acc[mt][nt][0], v1 = acc[mt][nt][1];
            float v2 = acc[mt][nt][2], v3 = acc[mt][nt][3];
            if (EPI == 1) {
                const float* ex0 = extra + (r0 >> 8) * EDIM;
                const float* ex1 = extra + (r1 >> 8) * EDIM;
                v0 = gelu_exact(v0 + ex0[c]); v1 = gelu_exact(v1 + ex0[c + 1]);
                v2 = gelu_exact(v2 + ex1[c]); v3 = gelu_exact(v3 + ex1[c + 1]);
            } else {
                float e0 = extra[c], e1 = extra[c + 1];
                v0 = gelu_exact(v0 + e0); v1 = gelu_exact(v1 + e1);
                v2 = gelu_exact(v2 + e0); v3 = gelu_exact(v3 + e1);
            }
            __half2 h01 = __floats2half2_rn(v0, v1);
            __half2 h23 = __floats2half2_rn(v2, v3);
            *(uint32_t*)(C + (size_t)r0 * N + c) = *(uint32_t*)&h01;
            *(uint32_t*)(C + (size_t)r1 * N + c) = *(uint32_t*)&h23;
        }
    }
}

// ======================= fp32 -> fp16 bulk convert ==========================
__global__ void f2h_k(const float* __restrict__ src, uint16_t* __restrict__ dst, int n4)
{
    int i = blockIdx.x * blockDim.x + threadIdx.x;
    if (i >= n4) return;
    float4 v = ((const float4*)src)[i];
    __half2 h0 = __floats2half2_rn(v.x, v.y);
    __half2 h1 = __floats2half2_rn(v.z, v.w);
    ((uint2*)dst)[i] = make_uint2(*(uint32_t*)&h0, *(uint32_t*)&h1);
}

// ======================= tiled weight transpose + fp16 ======================
// dst[n*K + k] = fp16(src[k*N + n]); 32x32 smem tiles, 256 threads.
__global__ void transposeW_t(const float* __restrict__ src, uint16_t* __restrict__ dst,
                             int K, int N)
{
    __shared__ float t[32][33];
    int n0 = blockIdx.x * 32, k0 = blockIdx.y * 32;
    int tx = threadIdx.x & 31, ty = threadIdx.x >> 5;   // ty 0..7
    #pragma unroll
    for (int j = 0; j < 32; j += 8)
        t[ty + j][tx] = src[(size_t)(k0 + ty + j) * N + n0 + tx];
    __syncthreads();
    #pragma unroll
    for (int j = 0; j < 32; j += 8) {
        __half h = __float2half(t[tx][ty + j]);
        dst[(size_t)(n0 + ty + j) * K + k0 + tx] = *(uint16_t*)&h;
    }
}

// ======================= qW precompute (split-K tf32 mma) ===================
__device__ __forceinline__ unsigned f2tf32(float x) {
    unsigned r;
    asm("cvt.rna.tf32.f32 %0, %1;" : "=r"(r) : "f"(x));
    return r;
}
__device__ __forceinline__ void mma_tf32(float* d, const unsigned* a, const unsigned* b) {
    asm volatile(
        "mma.sync.aligned.m16n8k8.row.col.f32.tf32.tf32.f32 "
        "{%0,%1,%2,%3}, {%4,%5,%6,%7}, {%8,%9}, {%0,%1,%2,%3};\n"
        : "+f"(d[0]), "+f"(d[1]), "+f"(d[2]), "+f"(d[3])
        : "r"(a[0]), "r"(a[1]), "r"(a[2]), "r"(a[3]), "r"(b[0]), "r"(b[1]));
}

// One CTA = one (N-tile, K-slice). Writes partials to parts[blockIdx.z].
// A = questions [128, 768]; B = W1_top [K, N] row-major. KSLICE = 128.
__global__ void __launch_bounds__(256) qw_gemm_splitk(
    const float* __restrict__ A, const float* __restrict__ B,
    float* __restrict__ parts, int N, int K)
{
    constexpr int BM = 128, BN = 128, BK = 32, KSLICE = 128;
    constexpr int APAD = 36, BPAD = 136;
    __shared__ unsigned As[BM * APAD];
    __shared__ unsigned Bs[BK * BPAD];

    const int bn = blockIdx.x * BN;
    const int kbeg = blockIdx.z * KSLICE;
    float* Cout = parts + (size_t)blockIdx.z * QW_ELEMS;

    const int tid = threadIdx.x, warp = tid >> 5, lane = tid & 31;
    const int gid = lane >> 2, tig = lane & 3;
    const int mwarp = (warp >> 2) * 64, nwarp = (warp & 3) * 32;

    float acc[4][4][4];
    #pragma unroll
    for (int mt = 0; mt < 4; mt++)
        #pragma unroll
        for (int nt = 0; nt < 4; nt++)
            #pragma unroll
            for (int r = 0; r < 4; r++) acc[mt][nt][r] = 0.0f;

    const float* Bptr = B + bn;
    for (int k0 = kbeg; k0 < kbeg + KSLICE; k0 += BK) {
        #pragma unroll
        for (int i = 0; i < 4; i++) {
            int idx = tid + i * 256;
            int ar = idx >> 3, kq = (idx & 7) * 4;
            float4 v = *(const float4*)(A + (size_t)ar * K + k0 + kq);
            unsigned* dst = &As[ar * APAD + kq];
            dst[0] = f2tf32(v.x); dst[1] = f2tf32(v.y);
            dst[2] = f2tf32(v.z); dst[3] = f2tf32(v.w);
        }
        #pragma unroll
        for (int i = 0; i < 4; i++) {
            int idx = tid + i * 256;
            int bk = idx >> 5, nq = (idx & 31) * 4;
            float4 v = *(const float4*)(Bptr + (size_t)(k0 + bk) * N + nq);
            unsigned* dst = &Bs[bk * BPAD + nq];
            dst[0] = f2tf32(v.x); dst[1] = f2tf32(v.y);
            dst[2] = f2tf32(v.z); dst[3] = f2tf32(v.w);
        }
        __syncthreads();
        #pragma unroll
        for (int ks = 0; ks < BK / 8; ks++) {
            const int k = ks * 8;
            unsigned af[4][4];
            #pragma unroll
            for (int mt = 0; mt < 4; mt++) {
                int m = mwarp + mt * 16;
                af[mt][0] = As[(m + gid)     * APAD + k + tig];
                af[mt][1] = As[(m + gid + 8) * APAD + k + tig];
                af[mt][2] = As[(m + gid)     * APAD + k + tig + 4];
                af[mt][3] = As[(m + gid + 8) * APAD + k + tig + 4];
            }
            unsigned bf[4][2];
            #pragma unroll
            for (int nt = 0; nt < 4; nt++) {
                int n = nwarp + nt * 8;
                bf[nt][0] = Bs[(k + tig)     * BPAD + n + gid];
                bf[nt][1] = Bs[(k + tig + 4) * BPAD + n + gid];
            }
            #pragma unroll
            for (int mt = 0; mt < 4; mt++)
                #pragma unroll
                for (int nt = 0; nt < 4; nt++)
                    mma_tf32(acc[mt][nt], af[mt], bf[nt]);
        }
        __syncthreads();
    }
    #pragma unroll
    for (int mt = 0; mt < 4; mt++)
        #pragma unroll
        for (int nt = 0; nt < 4; nt++) {
            int r0 = mwarp + mt * 16 + gid;
            int r1 = r0 + 8;
            int c  = bn + nwarp + nt * 8 + 2 * tig;
            *(float2*)(Cout + (size_t)r0 * N + c) =
                make_float2(acc[mt][nt][0], acc[mt][nt][1]);
            *(float2*)(Cout + (size_t)r1 * N + c) =
                make_float2(acc[mt][nt][2], acc[mt][nt][3]);
        }
}

// qW = b1 + sum of split-K partials (deterministic)
__global__ void qw_reduce_k(const float* __restrict__ parts, const float* __restrict__ b1,
                            float* __restrict__ qW)
{
    int i = blockIdx.x * blockDim.x + threadIdx.x;
    if (i >= QW_ELEMS) return;
    float s = b1[i % EDIM];
    #pragma unroll
    for (int p = 0; p < QW_SLICES; p++) s += parts[p * QW_ELEMS + i];
    qW[i] = s;
}

// ======================= logits + softmax (fp16 H2) =========================
__global__ void __launch_bounds__(256) logits_softmax_h(
    const uint16_t* __restrict__ H2h, const float* __restrict__ W3,
    const float* __restrict__ b3, float* __restrict__ preds)
{
    int warp = (blockIdx.x * blockDim.x + threadIdx.x) >> 5;
    int lane = threadIdx.x & 31;
    if (warp >= NROWS) return;

    const __half2* h2 = (const __half2*)(H2h + (size_t)warp * HDIM);
    float a0 = 0.f, a1 = 0.f, a2 = 0.f, a3 = 0.f;
    #pragma unroll
    for (int j = 0; j < HDIM / 64; j++) {
        int m = lane + j * 32;
        __half2 hv = h2[m];
        float x0 = __low2float(hv), x1 = __high2float(hv);
        float4 w0 = *(const float4*)(W3 + (2 * m) * 4);
        float4 w1 = *(const float4*)(W3 + (2 * m + 1) * 4);
        a0 = fmaf(x0, w0.x, fmaf(x1, w1.x, a0));
        a1 = fmaf(x0, w0.y, fmaf(x1, w1.y, a1));
        a2 = fmaf(x0, w0.z, fmaf(x1, w1.z, a2));
        a3 = fmaf(x0, w0.w, fmaf(x1, w1.w, a3));
    }
    #pragma unroll
    for (int off = 16; off; off >>= 1) {
        a0 += __shfl_xor_sync(0xffffffffu, a0, off);
        a1 += __shfl_xor_sync(0xffffffffu, a1, off);
        a2 += __shfl_xor_sync(0xffffffffu, a2, off);
        a3 += __shfl_xor_sync(0xffffffffu, a3, off);
    }
    if (lane == 0) {
        float l0 = a0 + b3[0], l1 = a1 + b3[1], l2 = a2 + b3[2], l3 = a3 + b3[3];
        float mx = fmaxf(fmaxf(l0, l1), fmaxf(l2, l3));
        float e0 = expf(l0 - mx), e1 = expf(l1 - mx), e2 = expf(l2 - mx), e3 = expf(l3 - mx);
        float inv = 1.0f / (e0 + e1 + e2 + e3);
        *(float4*)(preds + (size_t)warp * 4) =
            make_float4(e0 * inv, e1 * inv, e2 * inv, e3 * inv);
    }
}

// ======================= per-bag aggregation ================================
__global__ void aggregate_k(const float* __restrict__ preds,
                            const int* __restrict__ nseg,
                            float* __restrict__ out)
{
    int b = blockIdx.x;
    int c = threadIdx.x;
    __shared__ float ss[NCLS][SDIM];
    __shared__ float suf[NCLS][SDIM];
    if (c >= NCLS) return;

    int n = nseg[b];
    const float4* p = (const float4*)(preds + (size_t)b * SDIM * NCLS);

    for (int i = 0; i < n; i++) {
        float4 pv = p[i];
        float sv = (c == 0) ? 0.0f
                 : (c == 1) ? pv.x
                 : (c == 2) ? pv.x + pv.y
                            : pv.x + pv.y + pv.z;
        ss[c][i] = sv;
    }
    float r = 1.0f;
    for (int i = n - 1; i >= 0; i--) {
        suf[c][i] = r;
        r *= ss[c][i];
    }
    float pre = 1.0f, cpl = 1.0f, sum = 0.0f, prodp = 1.0f;
    for (int i = 0; i < n; i++) {
        float4 pv = p[i];
        float pc = (c == 0) ? pv.x : (c == 1) ? pv.y : (c == 2) ? pv.z : pv.w;
        float L = pre * suf[c][i];
        cpl *= L;
        sum = fmaf(pc, cpl, sum);
        prodp *= pc;
        pre *= ss[c][i];
    }
    out[b * NCLS + c] = sum * 0.25f + prodp;
}

// ===========================================================================
extern "C" void kernel_launch(void* const* d_in, const int* in_sizes, int n_in,
                              void* d_out, int out_size)
{
    const float* questions = (const float*)d_in[0];
    const float* segments  = (const float*)d_in[1];
    const float* W1        = (const float*)d_in[2];
    const float* b1        = (const float*)d_in[3];
    const float* W2        = (const float*)d_in[4];
    const float* b2        = (const float*)d_in[5];
    const float* W3        = (const float*)d_in[6];
    const float* b3        = (const float*)d_in[7];
    const int*   nseg      = (const int*)d_in[8];
    float* out = (float*)d_out;

    float *pqW, *pqWpart, *ppreds;
    uint16_t *psegh, *pH1h, *pH2h, *pW1T, *pW2T;
    cudaGetSymbolAddress((void**)&pqW,    g_qW);
    cudaGetSymbolAddress((void**)&pqWpart, g_qWpart);
    cudaGetSymbolAddress((void**)&psegh,  g_segh);
    cudaGetSymbolAddress((void**)&pH1h,   g_H1h);
    cudaGetSymbolAddress((void**)&pH2h,   g_H2h);
    cudaGetSymbolAddress((void**)&pW1T,   g_W1T);
    cudaGetSymbolAddress((void**)&pW2T,   g_W2T);
    cudaGetSymbolAddress((void**)&ppreds, g_preds);

    constexpr int GEMM_SMEM = 3 * 2 * 128 * 20 * 4;   // 61440 B
    cudaFuncSetAttribute(gemm_h<1>, cudaFuncAttributeMaxDynamicSharedMemorySize, GEMM_SMEM);
    cudaFuncSetAttribute(gemm_h<2>, cudaFuncAttributeMaxDynamicSharedMemorySize, GEMM_SMEM);

    // 0a) segments -> fp16
    f2h_k<<<((size_t)NROWS * EDIM / 4 + 255) / 256, 256>>>(
        segments, psegh, NROWS * EDIM / 4);
    // 0b) weight transpose + fp16 convert (tiled)
    transposeW_t<<<dim3(EDIM / 32, EDIM / 32), 256>>>(W1 + (size_t)EDIM * EDIM, pW1T, EDIM, EDIM);
    transposeW_t<<<dim3(HDIM / 32, EDIM / 32), 256>>>(W2, pW2T, EDIM, HDIM);

    // 1) qW = q @ W1_top + b1: split-K over 6 slices, then deterministic reduce
    qw_gemm_splitk<<<dim3(EDIM / 128, 1, QW_SLICES), 256>>>(
        questions, W1, pqWpart, EDIM, EDIM);
    qw_reduce_k<<<(QW_ELEMS + 255) / 256, 256>>>(pqWpart, b1, pqW);

    // 2) H1h = gelu(seg @ W1_botT^T + qW[b])   (fp16 mma, 3-stage pipeline)
    gemm_h<1><<<dim3(EDIM / 128, NROWS / 128), 256, GEMM_SMEM>>>(
        psegh, pW1T, pH1h, pqW, NROWS, EDIM, EDIM);

    // 3) H2h = gelu(H1h @ W2T^T + b2)
    gemm_h<2><<<dim3(HDIM / 128, NROWS / 128), 256, GEMM_SMEM>>>(
        pH1h, pW2T, pH2h, b2, NROWS, HDIM, EDIM);

    // 4) preds = softmax(H2h @ W3 + b3)
    logits_softmax_h<<<(NROWS * 32) / 256, 256>>>(pH2h, W3, b3, ppreds);

    // 5) per-bag aggregation
    aggregate_k<<<BATCH, 32>>>(ppreds, nseg, out);
}

// round 14
// speedup vs baseline: 5.7218x; 1.0744x over previous
#include <cuda_runtime.h>
#include <cuda_fp16.h>
#include <math.h>
#include <cstdint>

// Problem constants
#define EDIM   768
#define SDIM   256
#define BATCH  128
#define NROWS  (BATCH * SDIM)   // 32768
#define HDIM   (EDIM / 2)       // 384
#define NCLS   4
#define QW_SLICES 6
#define QW_ELEMS  (BATCH * EDIM)
#define NTILES_H2 (HDIM / 128)  // 3

// Scratch (static device globals — no allocation APIs allowed)
__device__ float    g_qW[QW_ELEMS];                         // q @ W1_top + b1 (fp32)
__device__ float    g_qWpart[QW_SLICES * QW_ELEMS];         // split-K partials
__device__ uint16_t g_segh[(size_t)NROWS * EDIM];           // segments fp16, 50 MB
__device__ uint16_t g_H1h[(size_t)NROWS * EDIM];            // fp16, 50 MB
__device__ uint16_t g_W1T[(size_t)EDIM * EDIM];             // W1 bottom, [N,K] fp16
__device__ uint16_t g_W2T[(size_t)HDIM * EDIM];             // W2 [N,K] fp16
__device__ float    g_lpart[NTILES_H2 * NROWS * NCLS];      // partial logits, 1.5 MB
__device__ float    g_preds[NROWS * NCLS];

__device__ __forceinline__ float gelu_exact(float x) {
    return 0.5f * x * (1.0f + erff(x * 0.70710678118654752f));
}

__device__ __forceinline__ uint32_t smem_u32(const void* p) {
    uint32_t a;
    asm("{ .reg .u64 t; cvta.to.shared.u64 t, %1; cvt.u32.u64 %0, t; }" : "=r"(a) : "l"(p));
    return a;
}
__device__ __forceinline__ void cp16(uint32_t saddr, const void* g) {
    asm volatile("cp.async.cg.shared.global [%0], [%1], 16;" :: "r"(saddr), "l"(g));
}
#define CP_COMMIT() asm volatile("cp.async.commit_group;" ::: "memory")
#define CP_WAIT2()  asm volatile("cp.async.wait_group 2;"  ::: "memory")
#define CP_WAIT0()  asm volatile("cp.async.wait_group 0;"  ::: "memory")

__device__ __forceinline__ void ldsm_x4(uint32_t* r, uint32_t addr) {
    asm volatile("ldmatrix.sync.aligned.m8n8.x4.shared.b16 {%0,%1,%2,%3}, [%4];"
                 : "=r"(r[0]), "=r"(r[1]), "=r"(r[2]), "=r"(r[3]) : "r"(addr));
}
// fp16 tensor-core mma: D[16x8] += A[16x16] * B[16x8], fp32 accumulate.
__device__ __forceinline__ void mma_f16(float* d, const uint32_t* a, const uint32_t* b) {
    asm volatile(
        "mma.sync.aligned.m16n8k16.row.col.f32.f16.f16.f32 "
        "{%0,%1,%2,%3}, {%4,%5,%6,%7}, {%8,%9}, {%0,%1,%2,%3};\n"
        : "+f"(d[0]), "+f"(d[1]), "+f"(d[2]), "+f"(d[3])
        : "r"(a[0]), "r"(a[1]), "r"(a[2]), "r"(a[3]), "r"(b[0]), "r"(b[1]));
}

// ---------------------------------------------------------------------------
// fp16 tensor-core GEMM, 4-stage cp.async pipeline + ldmatrix fragments.
// BM=BN=128, BK=32, 8 warps (2m x 4n), warp tile 64x32, mma m16n8k16.
// Tile rows: 16 data words + 4 pad = 20 words (LDSM conflict-free).
// Dynamic smem: 4 stages x 20480 B = 81920 B.
// EPI 1: gelu(x + extra[(row>>8)*EDIM + col]) -> fp16 C     (qW add; gemm1)
// EPI 2: gelu(x + extra[col]) -> partial logits via W3 -> lpart   (gemm2)
// All dims divide tiles exactly; K/32 >= 3.
// ---------------------------------------------------------------------------
template <int EPI>
__global__ void __launch_bounds__(256, 2) gemm_h(
    const uint16_t* __restrict__ A, const uint16_t* __restrict__ BT,
    uint16_t* __restrict__ C, const float* __restrict__ extra,
    const float* __restrict__ W3, float* __restrict__ lpart,
    int M, int N, int K)
{
    constexpr int BM = 128, BK = 32;
    constexpr int STRIDE = BK / 2 + 4;                 // 20 words/row
    constexpr int TILEB = BM * STRIDE * 4;             // 10240 bytes per tile
    constexpr int STAGEB = 2 * TILEB;                  // 20480 bytes per stage
    extern __shared__ uint32_t smem[];

    const int bm = blockIdx.y * BM;
    const int bn = blockIdx.x * BM;
    const int tid = threadIdx.x, warp = tid >> 5, lane = tid & 31;
    const int gid = lane >> 2;            // 0..7
    const int tig = lane & 3;             // 0..3
    const int mwarp = (warp >> 2) * 64;   // 0 or 64
    const int nwarp = (warp & 3) * 32;    // 0,32,64,96

    const uint32_t sb = smem_u32(smem);

    const int fr = tid >> 2;              // 0..63
    const int fq = tid & 3;               // 16B group in row
    const uint16_t* Abase = A + (size_t)bm * K;
    const uint16_t* Bbase = BT + (size_t)bn * K;

    const uint32_t a_off = ((mwarp + (lane & 15)) * STRIDE + ((lane & 16) ? 4 : 0)) * 4;
    const uint32_t b_off = TILEB + ((nwarp + ((lane & 16) ? 8 : 0) + (lane & 7)) * STRIDE
                            + ((lane & 8) ? 4 : 0)) * 4;

    float acc[4][4][4];
    #pragma unroll
    for (int mt = 0; mt < 4; mt++)
        #pragma unroll
        for (int nt = 0; nt < 4; nt++)
            #pragma unroll
            for (int r = 0; r < 4; r++) acc[mt][nt][r] = 0.0f;

    const int nkc = K / BK;

    // prologue: chunks 0,1,2 into stages 0,1,2
    #pragma unroll
    for (int pc = 0; pc < 3; pc++) {
        const uint16_t* Ab = Abase + pc * BK;
        const uint16_t* Bb = Bbase + pc * BK;
        uint32_t st = sb + pc * STAGEB;
        #pragma unroll
        for (int i = 0; i < 2; i++) {
            int r = fr + i * 64;
            uint32_t d = (r * STRIDE + fq * 4) * 4;
            cp16(st + d, Ab + (size_t)r * K + fq * 8);
            cp16(st + TILEB + d, Bb + (size_t)r * K + fq * 8);
        }
        CP_COMMIT();
    }

    int s = 0;   // stage of current chunk
    for (int kc = 0; kc < nkc; kc++) {
        CP_WAIT2();          // chunk kc landed (kc+1, kc+2 may be in flight)
        __syncthreads();     // all warps done computing kc-1 (stage being refilled)

        if (kc + 3 < nkc) {
            const uint16_t* Ab = Abase + (kc + 3) * BK;
            const uint16_t* Bb = Bbase + (kc + 3) * BK;
            uint32_t st = sb + ((s + 3) & 3) * STAGEB;
            #pragma unroll
            for (int i = 0; i < 2; i++) {
                int r = fr + i * 64;
                uint32_t d = (r * STRIDE + fq * 4) * 4;
                cp16(st + d, Ab + (size_t)r * K + fq * 8);
                cp16(st + TILEB + d, Bb + (size_t)r * K + fq * 8);
            }
        }
        CP_COMMIT();         // one group per iteration (possibly empty)

        const uint32_t abase = sb + s * STAGEB + a_off;
        const uint32_t bbase = sb + s * STAGEB + b_off;
        #pragma unroll
        for (int ks = 0; ks < 2; ks++) {
            uint32_t af[4][4];
            #pragma unroll
            for (int mt = 0; mt < 4; mt++)
                ldsm_x4(af[mt], abase + mt * (16 * STRIDE * 4) + ks * 32);
            uint32_t bf[4][2];
            ldsm_x4(&bf[0][0], bbase + ks * 32);                       // nt0, nt1
            ldsm_x4(&bf[2][0], bbase + 16 * STRIDE * 4 + ks * 32);     // nt2, nt3
            #pragma unroll
            for (int mt = 0; mt < 4; mt++)
                #pragma unroll
                for (int nt = 0; nt < 4; nt++)
                    mma_f16(acc[mt][nt], af[mt], bf[nt]);
        }
        s = (s + 1) & 3;
    }

    if (EPI == 1) {
        // ---- gemm1 epilogue: qW add + gelu -> fp16 C ----
        #pragma unroll
        for (int mt = 0; mt < 4; mt++) {
            #pragma unroll
            for (int nt = 0; nt < 4; nt++) {
                int r0 = bm + mwarp + mt * 16 + gid;
                int r1 = r0 + 8;
                int c  = bn + nwarp + nt * 8 + 2 * tig;
                const float* ex0 = extra + (r0 >> 8) * EDIM;
                const float* ex1 = extra + (r1 >> 8) * EDIM;
                float v0 = gelu_exact(acc[mt][nt][0] + ex0[c]);
                float v1 = gelu_exact(acc[mt][nt][1] + ex0[c + 1]);
                float v2 = gelu_exact(acc[mt][nt][2] + ex1[c]);
                float v3 = gelu_exact(acc[mt][nt][3] + ex1[c + 1]);
                __half2 h01 = __floats2half2_rn(v0, v1);
                __half2 h23 = __floats2half2_rn(v2, v3);
                *(uint32_t*)(C + (size_t)r0 * N + c) = *(uint32_t*)&h01;
                *(uint32_t*)(C + (size_t)r1 * N + c) = *(uint32_t*)&h23;
            }
        }
    } else {
        // ---- gemm2 epilogue: bias + gelu, then partial logits via W3 ----
        float pl0[4][4], pl1[4][4];      // [mt][cls]
        #pragma unroll
        for (int mt = 0; mt < 4; mt++)
            #pragma unroll
            for (int k = 0; k < 4; k++) { pl0[mt][k] = 0.f; pl1[mt][k] = 0.f; }

        #pragma unroll
        for (int mt = 0; mt < 4; mt++) {
            #pragma unroll
            for (int nt = 0; nt < 4; nt++) {
                int c  = bn + nwarp + nt * 8 + 2 * tig;
                float e0 = extra[c], e1 = extra[c + 1];
                float v0 = gelu_exact(acc[mt][nt][0] + e0);
                float v1 = gelu_exact(acc[mt][nt][1] + e1);
                float v2 = gelu_exact(acc[mt][nt][2] + e0);
                float v3 = gelu_exact(acc[mt][nt][3] + e1);
                float4 w0 = *(const float4*)(W3 + (size_t)c * NCLS);
                float4 w1 = *(const float4*)(W3 + (size_t)(c + 1) * NCLS);
                pl0[mt][0] = fmaf(v0, w0.x, fmaf(v1, w1.x, pl0[mt][0]));
                pl0[mt][1] = fmaf(v0, w0.y, fmaf(v1, w1.y, pl0[mt][1]));
                pl0[mt][2] = fmaf(v0, w0.z, fmaf(v1, w1.z, pl0[mt][2]));
                pl0[mt][3] = fmaf(v0, w0.w, fmaf(v1, w1.w, pl0[mt][3]));
                pl1[mt][0] = fmaf(v2, w0.x, fmaf(v3, w1.x, pl1[mt][0]));
                pl1[mt][1] = fmaf(v2, w0.y, fmaf(v3, w1.y, pl1[mt][1]));
                pl1[mt][2] = fmaf(v2, w0.z, fmaf(v3, w1.z, pl1[mt][2]));
                pl1[mt][3] = fmaf(v2, w0.w, fmaf(v3, w1.w, pl1[mt][3]));
            }
        }
        // quad reduce over tig (lane = gid*4 + tig)
        #pragma unroll
        for (int d = 1; d <= 2; d <<= 1) {
            #pragma unroll
            for (int mt = 0; mt < 4; mt++)
                #pragma unroll
                for (int k = 0; k < 4; k++) {
                    pl0[mt][k] += __shfl_xor_sync(0xffffffffu, pl0[mt][k], d);
                    pl1[mt][k] += __shfl_xor_sync(0xffffffffu, pl1[mt][k], d);
                }
        }
        // cross-warp reduce via smem (reuse pipeline stages; all cp.async done)
        CP_WAIT0();
        __syncthreads();
        float* red = (float*)smem;        // [4 nwarp][128 row][4 cls] = 8 KB
        if (tig == 0) {
            int nw = warp & 3;
            #pragma unroll
            for (int mt = 0; mt < 4; mt++) {
                int row0 = (warp >> 2) * 64 + mt * 16 + gid;
                *(float4*)&red[((nw * 128) + row0) * 4]     =
                    make_float4(pl0[mt][0], pl0[mt][1], pl0[mt][2], pl0[mt][3]);
                *(float4*)&red[((nw * 128) + row0 + 8) * 4] =
                    make_float4(pl1[mt][0], pl1[mt][1], pl1[mt][2], pl1[mt][3]);
            }
        }
        __syncthreads();
        if (tid < 128) {
            float4 s0 = *(float4*)&red[((0 * 128) + tid) * 4];
            float4 s1 = *(float4*)&red[((1 * 128) + tid) * 4];
            float4 s2 = *(float4*)&red[((2 * 128) + tid) * 4];
            float4 s3 = *(float4*)&red[((3 * 128) + tid) * 4];
            float4 t = make_float4(s0.x + s1.x + s2.x + s3.x,
                                   s0.y + s1.y + s2.y + s3.y,
                                   s0.z + s1.z + s2.z + s3.z,
                                   s0.w + s1.w + s2.w + s3.w);
            *(float4*)&lpart[((size_t)blockIdx.x * NROWS + bm + tid) * NCLS] = t;
        }
    }
}

// ======================= logits combine + softmax ===========================
__global__ void logits_combine_k(const float* __restrict__ lpart,
                                 const float* __restrict__ b3,
                                 float* __restrict__ preds)
{
    int i = blockIdx.x * blockDim.x + threadIdx.x;
    if (i >= NROWS) return;
    float4 a = *(const float4*)&lpart[(size_t)(0 * NROWS + i) * NCLS];
    float4 b = *(const float4*)&lpart[(size_t)(1 * NROWS + i) * NCLS];
    float4 c = *(const float4*)&lpart[(size_t)(2 * NROWS + i) * NCLS];
    float l0 = a.x + b.x + c.x + b3[0];
    float l1 = a.y + b.y + c.y + b3[1];
    float l2 = a.z + b.z + c.z + b3[2];
    float l3 = a.w + b.w + c.w + b3[3];
    float mx = fmaxf(fmaxf(l0, l1), fmaxf(l2, l3));
    float e0 = expf(l0 - mx), e1 = expf(l1 - mx), e2 = expf(l2 - mx), e3 = expf(l3 - mx);
    float inv = 1.0f / (e0 + e1 + e2 + e3);
    *(float4*)&preds[(size_t)i * NCLS] = make_float4(e0 * inv, e1 * inv, e2 * inv, e3 * inv);
}

// ======================= fp32 -> fp16 bulk convert (16B stores) =============
__global__ void f2h_k(const float* __restrict__ src, uint16_t* __restrict__ dst, int n8)
{
    int i = blockIdx.x * blockDim.x + threadIdx.x;
    if (i >= n8) return;
    float4 v0 = ((const float4*)src)[2 * i];
    float4 v1 = ((const float4*)src)[2 * i + 1];
    __half2 h0 = __floats2half2_rn(v0.x, v0.y);
    __half2 h1 = __floats2half2_rn(v0.z, v0.w);
    __half2 h2 = __floats2half2_rn(v1.x, v1.y);
    __half2 h3 = __floats2half2_rn(v1.z, v1.w);
    ((uint4*)dst)[i] = make_uint4(*(uint32_t*)&h0, *(uint32_t*)&h1,
                                  *(uint32_t*)&h2, *(uint32_t*)&h3);
}

// ======================= tiled weight transpose + fp16 ======================
__global__ void transposeW_t(const float* __restrict__ src, uint16_t* __restrict__ dst,
                             int K, int N)
{
    __shared__ float t[32][33];
    int n0 = blockIdx.x * 32, k0 = blockIdx.y * 32;
    int tx = threadIdx.x & 31, ty = threadIdx.x >> 5;
    #pragma unroll
    for (int j = 0; j < 32; j += 8)
        t[ty + j][tx] = src[(size_t)(k0 + ty + j) * N + n0 + tx];
    __syncthreads();
    #pragma unroll
    for (int j = 0; j < 32; j += 8) {
        __half h = __float2half(t[tx][ty + j]);
        dst[(size_t)(n0 + ty + j) * K + k0 + tx] = *(uint16_t*)&h;
    }
}

// ======================= qW precompute (split-K tf32 mma) ===================
__device__ __forceinline__ unsigned f2tf32(float x) {
    unsigned r;
    asm("cvt.rna.tf32.f32 %0, %1;" : "=r"(r) : "f"(x));
    return r;
}
__device__ __forceinline__ void mma_tf32(float* d, const unsigned* a, const unsigned* b) {
    asm volatile(
        "mma.sync.aligned.m16n8k8.row.col.f32.tf32.tf32.f32 "
        "{%0,%1,%2,%3}, {%4,%5,%6,%7}, {%8,%9}, {%0,%1,%2,%3};\n"
        : "+f"(d[0]), "+f"(d[1]), "+f"(d[2]), "+f"(d[3])
        : "r"(a[0]), "r"(a[1]), "r"(a[2]), "r"(a[3]), "r"(b[0]), "r"(b[1]));
}

__global__ void __launch_bounds__(256) qw_gemm_splitk(
    const float* __restrict__ A, const float* __restrict__ B,
    float* __restrict__ parts, int N, int K)
{
    constexpr int BM = 128, BN = 128, BK = 32, KSLICE = 128;
    constexpr int APAD = 36, BPAD = 136;
    __shared__ unsigned As[BM * APAD];
    __shared__ unsigned Bs[BK * BPAD];

    const int bn = blockIdx.x * BN;
    const int kbeg = blockIdx.z * KSLICE;
    float* Cout = parts + (size_t)blockIdx.z * QW_ELEMS;

    const int tid = threadIdx.x, warp = tid >> 5, lane = tid & 31;
    const int gid = lane >> 2, tig = lane & 3;
    const int mwarp = (warp >> 2) * 64, nwarp = (warp & 3) * 32;

    float acc[4][4][4];
    #pragma unroll
    for (int mt = 0; mt < 4; mt++)
        #pragma unroll
        for (int nt = 0; nt < 4; nt++)
            #pragma unroll
            for (int r = 0; r < 4; r++) acc[mt][nt][r] = 0.0f;

    const float* Bptr = B + bn;
    for (int k0 = kbeg; k0 < kbeg + KSLICE; k0 += BK) {
        #pragma unroll
        for (int i = 0; i < 4; i++) {
            int idx = tid + i * 256;
            int ar = idx >> 3, kq = (idx & 7) * 4;
            float4 v = *(const float4*)(A + (size_t)ar * K + k0 + kq);
            unsigned* dst = &As[ar * APAD + kq];
            dst[0] = f2tf32(v.x); dst[1] = f2tf32(v.y);
            dst[2] = f2tf32(v.z); dst[3] = f2tf32(v.w);
        }
        #pragma unroll
        for (int i = 0; i < 4; i++) {
            int idx = tid + i * 256;
            int bk = idx >> 5, nq = (idx & 31) * 4;
            float4 v = *(const float4*)(Bptr + (size_t)(k0 + bk) * N + nq);
            unsigned* dst = &Bs[bk * BPAD + nq];
            dst[0] = f2tf32(v.x); dst[1] = f2tf32(v.y);
            dst[2] = f2tf32(v.z); dst[3] = f2tf32(v.w);
        }
        __syncthreads();
        #pragma unroll
        for (int ks = 0; ks < BK / 8; ks++) {
            const int k = ks * 8;
            unsigned af[4][4];
            #pragma unroll
            for (int mt = 0; mt < 4; mt++) {
                int m = mwarp + mt * 16;
                af[mt][0] = As[(m + gid)     * APAD + k + tig];
                af[mt][1] = As[(m + gid + 8) * APAD + k + tig];
                af[mt][2] = As[(m + gid)     * APAD + k + tig + 4];
                af[mt][3] = As[(m + gid + 8) * APAD + k + tig + 4];
            }
            unsigned bf[4][2];
            #pragma unroll
            for (int nt = 0; nt < 4; nt++) {
                int n = nwarp + nt * 8;
                bf[nt][0] = Bs[(k + tig)     * BPAD + n + gid];
                bf[nt][1] = Bs[(k + tig + 4) * BPAD + n + gid];
            }
            #pragma unroll
            for (int mt = 0; mt < 4; mt++)
                #pragma unroll
                for (int nt = 0; nt < 4; nt++)
                    mma_tf32(acc[mt][nt], af[mt], bf[nt]);
        }
        __syncthreads();
    }
    #pragma unroll
    for (int mt = 0; mt < 4; mt++)
        #pragma unroll
        for (int nt = 0; nt < 4; nt++) {
            int r0 = mwarp + mt * 16 + gid;
            int r1 = r0 + 8;
            int c  = bn + nwarp + nt * 8 + 2 * tig;
            *(float2*)(Cout + (size_t)r0 * N + c) =
                make_float2(acc[mt][nt][0], acc[mt][nt][1]);
            *(float2*)(Cout + (size_t)r1 * N + c) =
                make_float2(acc[mt][nt][2], acc[mt][nt][3]);
        }
}

__global__ void qw_reduce_k(const float* __restrict__ parts, const float* __restrict__ b1,
                            float* __restrict__ qW)
{
    int i = blockIdx.x * blockDim.x + threadIdx.x;
    if (i >= QW_ELEMS) return;
    float s = b1[i % EDIM];
    #pragma unroll
    for (int p = 0; p < QW_SLICES; p++) s += parts[p * QW_ELEMS + i];
    qW[i] = s;
}

// ======================= per-bag aggregation ================================
__global__ void aggregate_k(const float* __restrict__ preds,
                            const int* __restrict__ nseg,
                            float* __restrict__ out)
{
    int b = blockIdx.x;
    int c = threadIdx.x;
    __shared__ float ss[NCLS][SDIM];
    __shared__ float suf[NCLS][SDIM];
    if (c >= NCLS) return;

    int n = nseg[b];
    const float4* p = (const float4*)(preds + (size_t)b * SDIM * NCLS);

    for (int i = 0; i < n; i++) {
        float4 pv = p[i];
        float sv = (c == 0) ? 0.0f
                 : (c == 1) ? pv.x
                 : (c == 2) ? pv.x + pv.y
                            : pv.x + pv.y + pv.z;
        ss[c][i] = sv;
    }
    float r = 1.0f;
    for (int i = n - 1; i >= 0; i--) {
        suf[c][i] = r;
        r *= ss[c][i];
    }
    float pre = 1.0f, cpl = 1.0f, sum = 0.0f, prodp = 1.0f;
    for (int i = 0; i < n; i++) {
        float4 pv = p[i];
        float pc = (c == 0) ? pv.x : (c == 1) ? pv.y : (c == 2) ? pv.z : pv.w;
        float L = pre * suf[c][i];
        cpl *= L;
        sum = fmaf(pc, cpl, sum);
        prodp *= pc;
        pre *= ss[c][i];
    }
    out[b * NCLS + c] = sum * 0.25f + prodp;
}

// ===========================================================================
extern "C" void kernel_launch(void* const* d_in, const int* in_sizes, int n_in,
                              void* d_out, int out_size)
{
    const float* questions = (const float*)d_in[0];
    const float* segments  = (const float*)d_in[1];
    const float* W1        = (const float*)d_in[2];
    const float* b1        = (const float*)d_in[3];
    const float* W2        = (const float*)d_in[4];
    const float* b2        = (const float*)d_in[5];
    const float* W3        = (const float*)d_in[6];
    const float* b3        = (const float*)d_in[7];
    const int*   nseg      = (const int*)d_in[8];
    float* out = (float*)d_out;

    float *pqW, *pqWpart, *plpart, *ppreds;
    uint16_t *psegh, *pH1h, *pW1T, *pW2T;
    cudaGetSymbolAddress((void**)&pqW,     g_qW);
    cudaGetSymbolAddress((void**)&pqWpart, g_qWpart);
    cudaGetSymbolAddress((void**)&psegh,   g_segh);
    cudaGetSymbolAddress((void**)&pH1h,    g_H1h);
    cudaGetSymbolAddress((void**)&pW1T,    g_W1T);
    cudaGetSymbolAddress((void**)&pW2T,    g_W2T);
    cudaGetSymbolAddress((void**)&plpart,  g_lpart);
    cudaGetSymbolAddress((void**)&ppreds,  g_preds);

    constexpr int GEMM_SMEM = 4 * 2 * 128 * 20 * 4;   // 81920 B
    cudaFuncSetAttribute(gemm_h<1>, cudaFuncAttributeMaxDynamicSharedMemorySize, GEMM_SMEM);
    cudaFuncSetAttribute(gemm_h<2>, cudaFuncAttributeMaxDynamicSharedMemorySize, GEMM_SMEM);

    // 0a) segments -> fp16
    f2h_k<<<((size_t)NROWS * EDIM / 8 + 255) / 256, 256>>>(
        segments, psegh, NROWS * EDIM / 8);
    // 0b) weight transpose + fp16 convert (tiled)
    transposeW_t<<<dim3(EDIM / 32, EDIM / 32), 256>>>(W1 + (size_t)EDIM * EDIM, pW1T, EDIM, EDIM);
    transposeW_t<<<dim3(HDIM / 32, EDIM / 32), 256>>>(W2, pW2T, EDIM, HDIM);

    // 1) qW = q @ W1_top + b1: split-K over 6 slices + deterministic reduce
    qw_gemm_splitk<<<dim3(EDIM / 128, 1, QW_SLICES), 256>>>(
        questions, W1, pqWpart, EDIM, EDIM);
    qw_reduce_k<<<(QW_ELEMS + 255) / 256, 256>>>(pqWpart, b1, pqW);

    // 2) H1h = gelu(seg @ W1_botT^T + qW[b])
    gemm_h<1><<<dim3(EDIM / 128, NROWS / 128), 256, GEMM_SMEM>>>(
        psegh, pW1T, pH1h, pqW, nullptr, nullptr, NROWS, EDIM, EDIM);

    // 3) partial logits = gelu(H1h @ W2T^T + b2) @ W3   (fused epilogue)
    gemm_h<2><<<dim3(HDIM / 128, NROWS / 128), 256, GEMM_SMEM>>>(
        pH1h, pW2T, nullptr, b2, W3, plpart, NROWS, HDIM, EDIM);

    // 4) preds = softmax(sum partials + b3)
    logits_combine_k<<<(NROWS + 255) / 256, 256>>>(plpart, b3, ppreds);

    // 5) per-bag aggregation
    aggregate_k<<<BATCH, 32>>>(ppreds, nseg, out);
}

// round 15
// speedup vs baseline: 6.0479x; 1.0570x over previous
#include <cuda_runtime.h>
#include <cuda_fp16.h>
#include <math.h>
#include <cstdint>

// Problem constants
#define EDIM   768
#define SDIM   256
#define BATCH  128
#define NROWS  (BATCH * SDIM)   // 32768
#define HDIM   (EDIM / 2)       // 384
#define NCLS   4
#define QW_SLICES 6
#define QW_ELEMS  (BATCH * EDIM)
#define NTILES_H2 (HDIM / 128)  // 3

// Scratch (static device globals — no allocation APIs allowed)
__device__ float    g_qW[QW_ELEMS];                         // q @ W1_top + b1 (fp32)
__device__ float    g_qWpart[QW_SLICES * QW_ELEMS];         // split-K partials
__device__ uint16_t g_segh[(size_t)NROWS * EDIM];           // segments fp16, 50 MB
__device__ uint16_t g_H1h[(size_t)NROWS * EDIM];            // fp16, 50 MB
__device__ uint16_t g_W1T[(size_t)EDIM * EDIM];             // W1 bottom, [N,K] fp16
__device__ uint16_t g_W2T[(size_t)HDIM * EDIM];             // W2 [N,K] fp16
__device__ float    g_lpart[NTILES_H2 * NROWS * NCLS];      // partial logits, 1.5 MB
__device__ float    g_preds[NROWS * NCLS];

__device__ __forceinline__ float gelu_exact(float x) {
    return 0.5f * x * (1.0f + erff(x * 0.70710678118654752f));
}

__device__ __forceinline__ uint32_t smem_u32(const void* p) {
    uint32_t a;
    asm("{ .reg .u64 t; cvta.to.shared.u64 t, %1; cvt.u32.u64 %0, t; }" : "=r"(a) : "l"(p));
    return a;
}
__device__ __forceinline__ void cp16(uint32_t saddr, const void* g) {
    asm volatile("cp.async.cg.shared.global [%0], [%1], 16;" :: "r"(saddr), "l"(g));
}
#define CP_COMMIT() asm volatile("cp.async.commit_group;" ::: "memory")
#define CP_WAIT1()  asm volatile("cp.async.wait_group 1;"  ::: "memory")
#define CP_WAIT0()  asm volatile("cp.async.wait_group 0;"  ::: "memory")

__device__ __forceinline__ void ldsm_x4(uint32_t* r, uint32_t addr) {
    asm volatile("ldmatrix.sync.aligned.m8n8.x4.shared.b16 {%0,%1,%2,%3}, [%4];"
                 : "=r"(r[0]), "=r"(r[1]), "=r"(r[2]), "=r"(r[3]) : "r"(addr));
}
// fp16 tensor-core mma: D[16x8] += A[16x16] * B[16x8], fp32 accumulate.
__device__ __forceinline__ void mma_f16(float* d, const uint32_t* a, const uint32_t* b) {
    asm volatile(
        "mma.sync.aligned.m16n8k16.row.col.f32.f16.f16.f32 "
        "{%0,%1,%2,%3}, {%4,%5,%6,%7}, {%8,%9}, {%0,%1,%2,%3};\n"
        : "+f"(d[0]), "+f"(d[1]), "+f"(d[2]), "+f"(d[3])
        : "r"(a[0]), "r"(a[1]), "r"(a[2]), "r"(a[3]), "r"(b[0]), "r"(b[1]));
}

// ---------------------------------------------------------------------------
// fp16 tensor-core GEMM, 4-stage cp.async pipeline + register-double-buffered
// ldmatrix fragments (LDSM for the next k-step / next chunk overlaps the MMAs
// of the current one). BM=BN=128, BK=32, 8 warps (2m x 4n), warp tile 64x32,
// mma m16n8k16. Tile rows: 16 data + 4 pad = 20 words (LDSM conflict-free).
// Dynamic smem: 4 stages x 20480 B = 81920 B.
// wait_group 1 at chunk boundary guarantees chunks kc AND kc+1 have landed,
// enabling the cross-chunk fragment prefetch. Stage-reuse safety: body kc
// reads stages s, s+1; writers target s+3; barrier at iteration bottom.
// EPI 1: gelu(x + extra[(row>>8)*EDIM + col]) -> fp16 C     (qW add; gemm1)
// EPI 2: gelu(x + extra[col]) -> partial logits via W3 -> lpart   (gemm2)
// All dims divide tiles exactly; K/32 >= 4.
// ---------------------------------------------------------------------------
template <int EPI>
__global__ void __launch_bounds__(256, 2) gemm_h(
    const uint16_t* __restrict__ A, const uint16_t* __restrict__ BT,
    uint16_t* __restrict__ C, const float* __restrict__ extra,
    const float* __restrict__ W3, float* __restrict__ lpart,
    int M, int N, int K)
{
    constexpr int BM = 128, BK = 32;
    constexpr int STRIDE = BK / 2 + 4;                 // 20 words/row
    constexpr int TILEB = BM * STRIDE * 4;             // 10240 bytes per tile
    constexpr int STAGEB = 2 * TILEB;                  // 20480 bytes per stage
    constexpr int ROWB16 = 16 * STRIDE * 4;            // 16 rows of words, bytes
    extern __shared__ uint32_t smem[];

    const int bm = blockIdx.y * BM;
    const int bn = blockIdx.x * BM;
    const int tid = threadIdx.x, warp = tid >> 5, lane = tid & 31;
    const int gid = lane >> 2;            // 0..7
    const int tig = lane & 3;             // 0..3
    const int mwarp = (warp >> 2) * 64;   // 0 or 64
    const int nwarp = (warp & 3) * 32;    // 0,32,64,96

    const uint32_t sb = smem_u32(smem);

    const int fr = tid >> 2;              // 0..63
    const int fq = tid & 3;               // 16B group in row
    const uint16_t* Abase = A + (size_t)bm * K;
    const uint16_t* Bbase = BT + (size_t)bn * K;

    const uint32_t a_off = ((mwarp + (lane & 15)) * STRIDE + ((lane & 16) ? 4 : 0)) * 4;
    const uint32_t b_off = TILEB + ((nwarp + ((lane & 16) ? 8 : 0) + (lane & 7)) * STRIDE
                            + ((lane & 8) ? 4 : 0)) * 4;

#define LOAD_FRAGS(af, bf, sbase, ko) do { \
    ldsm_x4(&af[0][0], (sbase) + a_off + 0 * ROWB16 + (ko)); \
    ldsm_x4(&af[1][0], (sbase) + a_off + 1 * ROWB16 + (ko)); \
    ldsm_x4(&af[2][0], (sbase) + a_off + 2 * ROWB16 + (ko)); \
    ldsm_x4(&af[3][0], (sbase) + a_off + 3 * ROWB16 + (ko)); \
    ldsm_x4(&bf[0][0], (sbase) + b_off + (ko)); \
    ldsm_x4(&bf[2][0], (sbase) + b_off + ROWB16 + (ko)); \
} while (0)

#define DO_MMA(af, bf) do { \
    _Pragma("unroll") \
    for (int mt = 0; mt < 4; mt++) \
        _Pragma("unroll") \
        for (int nt = 0; nt < 4; nt++) \
            mma_f16(acc[mt][nt], af[mt], bf[nt]); \
} while (0)

    float acc[4][4][4];
    #pragma unroll
    for (int mt = 0; mt < 4; mt++)
        #pragma unroll
        for (int nt = 0; nt < 4; nt++)
            #pragma unroll
            for (int r = 0; r < 4; r++) acc[mt][nt][r] = 0.0f;

    const int nkc = K / BK;

    // prologue: chunks 0,1,2 into stages 0,1,2
    #pragma unroll
    for (int pc = 0; pc < 3; pc++) {
        const uint16_t* Ab = Abase + pc * BK;
        const uint16_t* Bb = Bbase + pc * BK;
        uint32_t st = sb + pc * STAGEB;
        #pragma unroll
        for (int i = 0; i < 2; i++) {
            int r = fr + i * 64;
            uint32_t d = (r * STRIDE + fq * 4) * 4;
            cp16(st + d, Ab + (size_t)r * K + fq * 8);
            cp16(st + TILEB + d, Bb + (size_t)r * K + fq * 8);
        }
        CP_COMMIT();
    }

    uint32_t afA[4][4], bfA[4][2], afB[4][4], bfB[4][2];

    CP_WAIT1();              // chunks 0,1 landed (chunk 2 may be in flight)
    __syncthreads();
    LOAD_FRAGS(afA, bfA, sb, 0);          // (kc=0, ks=0) from stage 0

    int s = 0;   // stage of current chunk
    for (int kc = 0; kc < nkc; kc++) {
        const uint32_t sb_s  = sb + s * STAGEB;
        const uint32_t sb_s1 = sb + ((s + 1) & 3) * STAGEB;

        if (kc + 3 < nkc) {
            const uint16_t* Ab = Abase + (kc + 3) * BK;
            const uint16_t* Bb = Bbase + (kc + 3) * BK;
            uint32_t st = sb + ((s + 3) & 3) * STAGEB;
            #pragma unroll
            for (int i = 0; i < 2; i++) {
                int r = fr + i * 64;
                uint32_t d = (r * STRIDE + fq * 4) * 4;
                cp16(st + d, Ab + (size_t)r * K + fq * 8);
                cp16(st + TILEB + d, Bb + (size_t)r * K + fq * 8);
            }
        }
        CP_COMMIT();         // one group per iteration (possibly empty)

        LOAD_FRAGS(afB, bfB, sb_s, 32);   // (kc, ks=1) — overlaps MMA below
        DO_MMA(afA, bfA);                 // (kc, ks=0)
        LOAD_FRAGS(afA, bfA, sb_s1, 0);   // (kc+1, ks=0); stale read on last iter, unused
        DO_MMA(afB, bfB);                 // (kc, ks=1)

        s = (s + 1) & 3;
        if (kc + 1 < nkc) {
            CP_WAIT1();      // chunks <= kc+2 landed
            __syncthreads(); // stage reuse protection
        }
    }

    if (EPI == 1) {
        // ---- gemm1 epilogue: qW add + gelu -> fp16 C ----
        #pragma unroll
        for (int mt = 0; mt < 4; mt++) {
            #pragma unroll
            for (int nt = 0; nt < 4; nt++) {
                int r0 = bm + mwarp + mt * 16 + gid;
                int r1 = r0 + 8;
                int c  = bn + nwarp + nt * 8 + 2 * tig;
                const float* ex0 = extra + (r0 >> 8) * EDIM;
                const float* ex1 = extra + (r1 >> 8) * EDIM;
                float v0 = gelu_exact(acc[mt][nt][0] + ex0[c]);
                float v1 = gelu_exact(acc[mt][nt][1] + ex0[c + 1]);
                float v2 = gelu_exact(acc[mt][nt][2] + ex1[c]);
                float v3 = gelu_exact(acc[mt][nt][3] + ex1[c + 1]);
                __half2 h01 = __floats2half2_rn(v0, v1);
                __half2 h23 = __floats2half2_rn(v2, v3);
                *(uint32_t*)(C + (size_t)r0 * N + c) = *(uint32_t*)&h01;
                *(uint32_t*)(C + (size_t)r1 * N + c) = *(uint32_t*)&h23;
            }
        }
    } else {
        // ---- gemm2 epilogue: bias + gelu, then partial logits via W3 ----
        float pl0[4][4], pl1[4][4];      // [mt][cls]
        #pragma unroll
        for (int mt = 0; mt < 4; mt++)
            #pragma unroll
            for (int k = 0; k < 4; k++) { pl0[mt][k] = 0.f; pl1[mt][k] = 0.f; }

        #pragma unroll
        for (int mt = 0; mt < 4; mt++) {
            #pragma unroll
            for (int nt = 0; nt < 4; nt++) {
                int c  = bn + nwarp + nt * 8 + 2 * tig;
                float e0 = extra[c], e1 = extra[c + 1];
                float v0 = gelu_exact(acc[mt][nt][0] + e0);
                float v1 = gelu_exact(acc[mt][nt][1] + e1);
                float v2 = gelu_exact(acc[mt][nt][2] + e0);
                float v3 = gelu_exact(acc[mt][nt][3] + e1);
                float4 w0 = *(const float4*)(W3 + (size_t)c * NCLS);
                float4 w1 = *(const float4*)(W3 + (size_t)(c + 1) * NCLS);
                pl0[mt][0] = fmaf(v0, w0.x, fmaf(v1, w1.x, pl0[mt][0]));
                pl0[mt][1] = fmaf(v0, w0.y, fmaf(v1, w1.y, pl0[mt][1]));
                pl0[mt][2] = fmaf(v0, w0.z, fmaf(v1, w1.z, pl0[mt][2]));
                pl0[mt][3] = fmaf(v0, w0.w, fmaf(v1, w1.w, pl0[mt][3]));
                pl1[mt][0] = fmaf(v2, w0.x, fmaf(v3, w1.x, pl1[mt][0]));
                pl1[mt][1] = fmaf(v2, w0.y, fmaf(v3, w1.y, pl1[mt][1]));
                pl1[mt][2] = fmaf(v2, w0.z, fmaf(v3, w1.z, pl1[mt][2]));
                pl1[mt][3] = fmaf(v2, w0.w, fmaf(v3, w1.w, pl1[mt][3]));
            }
        }
        // quad reduce over tig (lane = gid*4 + tig)
        #pragma unroll
        for (int d = 1; d <= 2; d <<= 1) {
            #pragma unroll
            for (int mt = 0; mt < 4; mt++)
                #pragma unroll
                for (int k = 0; k < 4; k++) {
                    pl0[mt][k] += __shfl_xor_sync(0xffffffffu, pl0[mt][k], d);
                    pl1[mt][k] += __shfl_xor_sync(0xffffffffu, pl1[mt][k], d);
                }
        }
        // cross-warp reduce via smem (reuse pipeline stages; all cp.async done)
        CP_WAIT0();
        __syncthreads();
        float* red = (float*)smem;        // [4 nwarp][128 row][4 cls] = 8 KB
        if (tig == 0) {
            int nw = warp & 3;
            #pragma unroll
            for (int mt = 0; mt < 4; mt++) {
                int row0 = (warp >> 2) * 64 + mt * 16 + gid;
                *(float4*)&red[((nw * 128) + row0) * 4]     =
                    make_float4(pl0[mt][0], pl0[mt][1], pl0[mt][2], pl0[mt][3]);
                *(float4*)&red[((nw * 128) + row0 + 8) * 4] =
                    make_float4(pl1[mt][0], pl1[mt][1], pl1[mt][2], pl1[mt][3]);
            }
        }
        __syncthreads();
        if (tid < 128) {
            float4 s0 = *(float4*)&red[((0 * 128) + tid) * 4];
            float4 s1 = *(float4*)&red[((1 * 128) + tid) * 4];
            float4 s2 = *(float4*)&red[((2 * 128) + tid) * 4];
            float4 s3 = *(float4*)&red[((3 * 128) + tid) * 4];
            float4 t = make_float4(s0.x + s1.x + s2.x + s3.x,
                                   s0.y + s1.y + s2.y + s3.y,
                                   s0.z + s1.z + s2.z + s3.z,
                                   s0.w + s1.w + s2.w + s3.w);
            *(float4*)&lpart[((size_t)blockIdx.x * NROWS + bm + tid) * NCLS] = t;
        }
    }
#undef LOAD_FRAGS
#undef DO_MMA
}

// ======================= logits combine + softmax ===========================
__global__ void logits_combine_k(const float* __restrict__ lpart,
                                 const float* __restrict__ b3,
                                 float* __restrict__ preds)
{
    int i = blockIdx.x * blockDim.x + threadIdx.x;
    if (i >= NROWS) return;
    float4 a = *(const float4*)&lpart[(size_t)(0 * NROWS + i) * NCLS];
    float4 b = *(const float4*)&lpart[(size_t)(1 * NROWS + i) * NCLS];
    float4 c = *(const float4*)&lpart[(size_t)(2 * NROWS + i) * NCLS];
    float l0 = a.x + b.x + c.x + b3[0];
    float l1 = a.y + b.y + c.y + b3[1];
    float l2 = a.z + b.z + c.z + b3[2];
    float l3 = a.w + b.w + c.w + b3[3];
    float mx = fmaxf(fmaxf(l0, l1), fmaxf(l2, l3));
    float e0 = expf(l0 - mx), e1 = expf(l1 - mx), e2 = expf(l2 - mx), e3 = expf(l3 - mx);
    float inv = 1.0f / (e0 + e1 + e2 + e3);
    *(float4*)&preds[(size_t)i * NCLS] = make_float4(e0 * inv, e1 * inv, e2 * inv, e3 * inv);
}

// ======================= fp32 -> fp16 bulk convert (16B stores) =============
__global__ void f2h_k(const float* __restrict__ src, uint16_t* __restrict__ dst, int n8)
{
    int i = blockIdx.x * blockDim.x + threadIdx.x;
    if (i >= n8) return;
    float4 v0 = ((const float4*)src)[2 * i];
    float4 v1 = ((const float4*)src)[2 * i + 1];
    __half2 h0 = __floats2half2_rn(v0.x, v0.y);
    __half2 h1 = __floats2half2_rn(v0.z, v0.w);
    __half2 h2 = __floats2half2_rn(v1.x, v1.y);
    __half2 h3 = __floats2half2_rn(v1.z, v1.w);
    ((uint4*)dst)[i] = make_uint4(*(uint32_t*)&h0, *(uint32_t*)&h1,
                                  *(uint32_t*)&h2, *(uint32_t*)&h3);
}

// ======================= tiled weight transpose + fp16 ======================
__global__ void transposeW_t(const float* __restrict__ src, uint16_t* __restrict__ dst,
                             int K, int N)
{
    __shared__ float t[32][33];
    int n0 = blockIdx.x * 32, k0 = blockIdx.y * 32;
    int tx = threadIdx.x & 31, ty = threadIdx.x >> 5;
    #pragma unroll
    for (int j = 0; j < 32; j += 8)
        t[ty + j][tx] = src[(size_t)(k0 + ty + j) * N + n0 + tx];
    __syncthreads();
    #pragma unroll
    for (int j = 0; j < 32; j += 8) {
        __half h = __float2half(t[tx][ty + j]);
        dst[(size_t)(n0 + ty + j) * K + k0 + tx] = *(uint16_t*)&h;
    }
}

// ======================= qW precompute (split-K tf32 mma) ===================
__device__ __forceinline__ unsigned f2tf32(float x) {
    unsigned r;
    asm("cvt.rna.tf32.f32 %0, %1;" : "=r"(r) : "f"(x));
    return r;
}
__device__ __forceinline__ void mma_tf32(float* d, const unsigned* a, const unsigned* b) {
    asm volatile(
        "mma.sync.aligned.m16n8k8.row.col.f32.tf32.tf32.f32 "
        "{%0,%1,%2,%3}, {%4,%5,%6,%7}, {%8,%9}, {%0,%1,%2,%3};\n"
        : "+f"(d[0]), "+f"(d[1]), "+f"(d[2]), "+f"(d[3])
        : "r"(a[0]), "r"(a[1]), "r"(a[2]), "r"(a[3]), "r"(b[0]), "r"(b[1]));
}

__global__ void __launch_bounds__(256) qw_gemm_splitk(
    const float* __restrict__ A, const float* __restrict__ B,
    float* __restrict__ parts, int N, int K)
{
    constexpr int BM = 128, BN = 128, BK = 32, KSLICE = 128;
    constexpr int APAD = 36, BPAD = 136;
    __shared__ unsigned As[BM * APAD];
    __shared__ unsigned Bs[BK * BPAD];

    const int bn = blockIdx.x * BN;
    const int kbeg = blockIdx.z * KSLICE;
    float* Cout = parts + (size_t)blockIdx.z * QW_ELEMS;

    const int tid = threadIdx.x, warp = tid >> 5, lane = tid & 31;
    const int gid = lane >> 2, tig = lane & 3;
    const int mwarp = (warp >> 2) * 64, nwarp = (warp & 3) * 32;

    float acc[4][4][4];
    #pragma unroll
    for (int mt = 0; mt < 4; mt++)
        #pragma unroll
        for (int nt = 0; nt < 4; nt++)
            #pragma unroll
            for (int r = 0; r < 4; r++) acc[mt][nt][r] = 0.0f;

    const float* Bptr = B + bn;
    for (int k0 = kbeg; k0 < kbeg + KSLICE; k0 += BK) {
        #pragma unroll
        for (int i = 0; i < 4; i++) {
            int idx = tid + i * 256;
            int ar = idx >> 3, kq = (idx & 7) * 4;
            float4 v = *(const float4*)(A + (size_t)ar * K + k0 + kq);
            unsigned* dst = &As[ar * APAD + kq];
            dst[0] = f2tf32(v.x); dst[1] = f2tf32(v.y);
            dst[2] = f2tf32(v.z); dst[3] = f2tf32(v.w);
        }
        #pragma unroll
        for (int i = 0; i < 4; i++) {
            int idx = tid + i * 256;
            int bk = idx >> 5, nq = (idx & 31) * 4;
            float4 v = *(const float4*)(Bptr + (size_t)(k0 + bk) * N + nq);
            unsigned* dst = &Bs[bk * BPAD + nq];
            dst[0] = f2tf32(v.x); dst[1] = f2tf32(v.y);
            dst[2] = f2tf32(v.z); dst[3] = f2tf32(v.w);
        }
        __syncthreads();
        #pragma unroll
        for (int ks = 0; ks < BK / 8; ks++) {
            const int k = ks * 8;
            unsigned af[4][4];
            #pragma unroll
            for (int mt = 0; mt < 4; mt++) {
                int m = mwarp + mt * 16;
                af[mt][0] = As[(m + gid)     * APAD + k + tig];
                af[mt][1] = As[(m + gid + 8) * APAD + k + tig];
                af[mt][2] = As[(m + gid)     * APAD + k + tig + 4];
                af[mt][3] = As[(m + gid + 8) * APAD + k + tig + 4];
            }
            unsigned bf[4][2];
            #pragma unroll
            for (int nt = 0; nt < 4; nt++) {
                int n = nwarp + nt * 8;
                bf[nt][0] = Bs[(k + tig)     * BPAD + n + gid];
                bf[nt][1] = Bs[(k + tig + 4) * BPAD + n + gid];
            }
            #pragma unroll
            for (int mt = 0; mt < 4; mt++)
                #pragma unroll
                for (int nt = 0; nt < 4; nt++)
                    mma_tf32(acc[mt][nt], af[mt], bf[nt]);
        }
        __syncthreads();
    }
    #pragma unroll
    for (int mt = 0; mt < 4; mt++)
        #pragma unroll
        for (int nt = 0; nt < 4; nt++) {
            int r0 = mwarp + mt * 16 + gid;
            int r1 = r0 + 8;
            int c  = bn + nwarp + nt * 8 + 2 * tig;
            *(float2*)(Cout + (size_t)r0 * N + c) =
                make_float2(acc[mt][nt][0], acc[mt][nt][1]);
            *(float2*)(Cout + (size_t)r1 * N + c) =
                make_float2(acc[mt][nt][2], acc[mt][nt][3]);
        }
}

__global__ void qw_reduce_k(const float* __restrict__ parts, const float* __restrict__ b1,
                            float* __restrict__ qW)
{
    int i = blockIdx.x * blockDim.x + threadIdx.x;
    if (i >= QW_ELEMS) return;
    float s = b1[i % EDIM];
    #pragma unroll
    for (int p = 0; p < QW_SLICES; p++) s += parts[p * QW_ELEMS + i];
    qW[i] = s;
}

// ======================= per-bag aggregation ================================
__global__ void aggregate_k(const float* __restrict__ preds,
                            const int* __restrict__ nseg,
                            float* __restrict__ out)
{
    int b = blockIdx.x;
    int c = threadIdx.x;
    __shared__ float ss[NCLS][SDIM];
    __shared__ float suf[NCLS][SDIM];
    if (c >= NCLS) return;

    int n = nseg[b];
    const float4* p = (const float4*)(preds + (size_t)b * SDIM * NCLS);

    for (int i = 0; i < n; i++) {
        float4 pv = p[i];
        float sv = (c == 0) ? 0.0f
                 : (c == 1) ? pv.x
                 : (c == 2) ? pv.x + pv.y
                            : pv.x + pv.y + pv.z;
        ss[c][i] = sv;
    }
    float r = 1.0f;
    for (int i = n - 1; i >= 0; i--) {
        suf[c][i] = r;
        r *= ss[c][i];
    }
    float pre = 1.0f, cpl = 1.0f, sum = 0.0f, prodp = 1.0f;
    for (int i = 0; i < n; i++) {
        float4 pv = p[i];
        float pc = (c == 0) ? pv.x : (c == 1) ? pv.y : (c == 2) ? pv.z : pv.w;
        float L = pre * suf[c][i];
        cpl *= L;
        sum = fmaf(pc, cpl, sum);
        prodp *= pc;
        pre *= ss[c][i];
    }
    out[b * NCLS + c] = sum * 0.25f + prodp;
}

// ===========================================================================
extern "C" void kernel_launch(void* const* d_in, const int* in_sizes, int n_in,
                              void* d_out, int out_size)
{
    const float* questions = (const float*)d_in[0];
    const float* segments  = (const float*)d_in[1];
    const float* W1        = (const float*)d_in[2];
    const float* b1        = (const float*)d_in[3];
    const float* W2        = (const float*)d_in[4];
    const float* b2        = (const float*)d_in[5];
    const float* W3        = (const float*)d_in[6];
    const float* b3        = (const float*)d_in[7];
    const int*   nseg      = (const int*)d_in[8];
    float* out = (float*)d_out;

    float *pqW, *pqWpart, *plpart, *ppreds;
    uint16_t *psegh, *pH1h, *pW1T, *pW2T;
    cudaGetSymbolAddress((void**)&pqW,     g_qW);
    cudaGetSymbolAddress((void**)&pqWpart, g_qWpart);
    cudaGetSymbolAddress((void**)&psegh,   g_segh);
    cudaGetSymbolAddress((void**)&pH1h,    g_H1h);
    cudaGetSymbolAddress((void**)&pW1T,    g_W1T);
    cudaGetSymbolAddress((void**)&pW2T,    g_W2T);
    cudaGetSymbolAddress((void**)&plpart,  g_lpart);
    cudaGetSymbolAddress((void**)&ppreds,  g_preds);

    constexpr int GEMM_SMEM = 4 * 2 * 128 * 20 * 4;   // 81920 B
    cudaFuncSetAttribute(gemm_h<1>, cudaFuncAttributeMaxDynamicSharedMemorySize, GEMM_SMEM);
    cudaFuncSetAttribute(gemm_h<2>, cudaFuncAttributeMaxDynamicSharedMemorySize, GEMM_SMEM);

    // 0a) segments -> fp16
    f2h_k<<<((size_t)NROWS * EDIM / 8 + 255) / 256, 256>>>(
        segments, psegh, NROWS * EDIM / 8);
    // 0b) weight transpose + fp16 convert (tiled)
    transposeW_t<<<dim3(EDIM / 32, EDIM / 32), 256>>>(W1 + (size_t)EDIM * EDIM, pW1T, EDIM, EDIM);
    transposeW_t<<<dim3(HDIM / 32, EDIM / 32), 256>>>(W2, pW2T, EDIM, HDIM);

    // 1) qW = q @ W1_top + b1: split-K over 6 slices + deterministic reduce
    qw_gemm_splitk<<<dim3(EDIM / 128, 1, QW_SLICES), 256>>>(
        questions, W1, pqWpart, EDIM, EDIM);
    qw_reduce_k<<<(QW_ELEMS + 255) / 256, 256>>>(pqWpart, b1, pqW);

    // 2) H1h = gelu(seg @ W1_botT^T + qW[b])
    gemm_h<1><<<dim3(EDIM / 128, NROWS / 128), 256, GEMM_SMEM>>>(
        psegh, pW1T, pH1h, pqW, nullptr, nullptr, NROWS, EDIM, EDIM);

    // 3) partial logits = gelu(H1h @ W2T^T + b2) @ W3   (fused epilogue)
    gemm_h<2><<<dim3(HDIM / 128, NROWS / 128), 256, GEMM_SMEM>>>(
        pH1h, pW2T, nullptr, b2, W3, plpart, NROWS, HDIM, EDIM);

    // 4) preds = softmax(sum partials + b3)
    logits_combine_k<<<(NROWS + 255) / 256, 256>>>(plpart, b3, ppreds);

    // 5) per-bag aggregation
    aggregate_k<<<BATCH, 32>>>(ppreds, nseg, out);
}